// round 13
// baseline (speedup 1.0000x reference)
#include <cuda_runtime.h>
#include <cuda_fp16.h>
#include <math.h>
#include <stdint.h>

// Problem constants
#define BB 4
#define CIN 256
#define CI 128
#define NN 4096          // H*W = 64*64
#define CP 384           // 3*CI projection channels
#define COUT 256
#define BN_EPS 1e-5f
#define NTILES 32        // NN / 128 key tiles

// Scratch (static device globals; allocation APIs are forbidden)
__device__ float d_proj[CP * BB * NN];     // [m][b][n]
__device__ float d_psum[CP];
__device__ float d_psumsq[CP];
__device__ float d_z[COUT * BB * NN];      // [o][b][n]
__device__ float d_zsum[COUT];
__device__ float d_zsumsq[COUT];

// fp16 hi/lo split operands
__device__ __half d_xt_hi[BB * NN * CIN];  // x^T      [b][n][c]
__device__ __half d_xt_lo[BB * NN * CIN];
__device__ __half d_th_hi[BB * NN * CI];   // theta^T  [b][n][c]
__device__ __half d_th_lo[BB * NN * CI];
__device__ __half d_ph_hi[BB * NN * CI];   // phi^T    [b][n][c]
__device__ __half d_ph_lo[BB * NN * CI];
__device__ __half d_g_hi[BB * CI * NN];    // g        [b][c][n]
__device__ __half d_y_hi[BB * NN * CI];    // y^T      [b][n][c]
__device__ __half d_y_lo[BB * NN * CI];

// ======================= helpers =======================
__device__ __forceinline__ uint32_t smem_u32(const void* p) {
    uint32_t a;
    asm("{ .reg .u64 t; cvta.to.shared.u64 t, %1; cvt.u32.u64 %0, t; }" : "=r"(a) : "l"(p));
    return a;
}

__device__ __forceinline__ void ldsm4(uint32_t& r0, uint32_t& r1, uint32_t& r2, uint32_t& r3,
                                      uint32_t addr) {
    asm volatile("ldmatrix.sync.aligned.m8n8.x4.shared.b16 {%0,%1,%2,%3}, [%4];"
                 : "=r"(r0), "=r"(r1), "=r"(r2), "=r"(r3) : "r"(addr));
}

__device__ __forceinline__ void mma16816(float* d, uint32_t a0, uint32_t a1, uint32_t a2, uint32_t a3,
                                         uint32_t b0, uint32_t b1) {
    asm volatile(
        "mma.sync.aligned.m16n8k16.row.col.f32.f16.f16.f32 "
        "{%0,%1,%2,%3}, {%4,%5,%6,%7}, {%8,%9}, {%0,%1,%2,%3};"
        : "+f"(d[0]), "+f"(d[1]), "+f"(d[2]), "+f"(d[3])
        : "r"(a0), "r"(a1), "r"(a2), "r"(a3), "r"(b0), "r"(b1));
}

__device__ __forceinline__ uint32_t sw_addr(uint32_t base, int row, int chunk) {
    return base + (uint32_t)row * 256u + (uint32_t)((chunk ^ (row & 7)) << 4);
}

__device__ __forceinline__ uint32_t packh2(__half a, __half b) {
    __half2 h = __halves2half2(a, b);
    return *(uint32_t*)&h;
}

__device__ __forceinline__ void cpasync16(uint32_t dst, const void* src) {
    asm volatile("cp.async.cg.shared.global [%0], [%1], 16;" :: "r"(dst), "l"(src));
}
#define CP_COMMIT()   asm volatile("cp.async.commit_group;" ::: "memory")
#define CP_WAIT_ALL() asm volatile("cp.async.wait_group 0;" ::: "memory")
#define CP_WAIT_1()   asm volatile("cp.async.wait_group 1;" ::: "memory")

// 256-thread cooperative tile loaders (for GEMM kernels)
__device__ __forceinline__ void load_tile(uint32_t dst, const __half* __restrict__ src,
                                          int row_stride) {
    const int t = threadIdx.x;
#pragma unroll
    for (int i = 0; i < 8; i++) {
        int cid = i * 256 + t;
        int row = cid >> 4, c = cid & 15;
        uint4 v = *(const uint4*)(src + (size_t)row * row_stride + c * 8);
        uint32_t a = sw_addr(dst, row, c);
        asm volatile("st.shared.v4.b32 [%0], {%1, %2, %3, %4};"
                     :: "r"(a), "r"(v.x), "r"(v.y), "r"(v.z), "r"(v.w));
    }
}

// 128-thread async loaders (attention)
__device__ __forceinline__ void load_tile128_a128(uint32_t dst, const __half* __restrict__ src,
                                                  int row_stride) {
    const int t = threadIdx.x;
#pragma unroll
    for (int i = 0; i < 16; i++) {
        int cid = i * 128 + t;
        int row = cid >> 4, c = cid & 15;
        cpasync16(sw_addr(dst, row, c), src + (size_t)row * row_stride + c * 8);
    }
}
__device__ __forceinline__ void load_tile64_a128(uint32_t dst, const __half* __restrict__ src,
                                                 int row_stride) {
    const int t = threadIdx.x;
#pragma unroll
    for (int i = 0; i < 8; i++) {
        int cid = i * 128 + t;
        int row = cid >> 4, c = cid & 15;
        cpasync16(sw_addr(dst, row, c), src + (size_t)row * row_stride + c * 8);
    }
}

__device__ __forceinline__ void split_tile(uint32_t dhi, uint32_t dlo,
                                           const float* __restrict__ src, int row_stride) {
    const int t = threadIdx.x;
#pragma unroll
    for (int i = 0; i < 8; i++) {
        int cid = i * 256 + t;
        int row = cid >> 4, c = cid & 15;
        const float* p = src + (size_t)row * row_stride + c * 8;
        float4 v0 = *(const float4*)p;
        float4 v1 = *(const float4*)(p + 4);
        float e[8] = {v0.x, v0.y, v0.z, v0.w, v1.x, v1.y, v1.z, v1.w};
        __half h[8], l[8];
#pragma unroll
        for (int j = 0; j < 8; j++) {
            h[j] = __float2half_rn(e[j]);
            l[j] = __float2half_rn(e[j] - __half2float(h[j]));
        }
        asm volatile("st.shared.v4.b32 [%0], {%1, %2, %3, %4};"
                     :: "r"(sw_addr(dhi, row, c)), "r"(packh2(h[0], h[1])), "r"(packh2(h[2], h[3])),
                        "r"(packh2(h[4], h[5])), "r"(packh2(h[6], h[7])));
        asm volatile("st.shared.v4.b32 [%0], {%1, %2, %3, %4};"
                     :: "r"(sw_addr(dlo, row, c)), "r"(packh2(l[0], l[1])), "r"(packh2(l[2], l[3])),
                        "r"(packh2(l[4], l[5])), "r"(packh2(l[6], l[7])));
    }
}

// ---------------- Kernel 0: transpose+split x (+ zero stats in block 0) ----------------
__global__ __launch_bounds__(256) void prep_xt_kernel(const float* __restrict__ x)
{
    __shared__ float tile[32][33];
    const int t = threadIdx.x;
    if (blockIdx.x == 0 && blockIdx.y == 0 && blockIdx.z == 0) {
        for (int i = t; i < CP; i += 256) { d_psum[i] = 0.0f; d_psumsq[i] = 0.0f; }
        if (t < COUT) { d_zsum[t] = 0.0f; d_zsumsq[t] = 0.0f; }
    }
    const int tx = t & 31, ty = t >> 5;
    const int b = blockIdx.z;
    const int c0 = blockIdx.y * 32;
    const int n0 = blockIdx.x * 32;
#pragma unroll
    for (int i = 0; i < 4; i++) {
        int c = c0 + ty + i * 8;
        tile[ty + i * 8][tx] = x[(size_t)(b * CIN + c) * NN + n0 + tx];
    }
    __syncthreads();
#pragma unroll
    for (int i = 0; i < 4; i++) {
        int n = n0 + ty + i * 8;
        float v = tile[tx][ty + i * 8];
        __half h = __float2half_rn(v);
        __half l = __float2half_rn(v - __half2float(h));
        size_t idx = (size_t)(b * NN + n) * CIN + c0 + tx;
        d_xt_hi[idx] = h;
        d_xt_lo[idx] = l;
    }
}

// ---------------- Kernel 1: tensor-core projection GEMM + fused stats ----------------
#define TG_A_HI 0
#define TG_A_LO 32768
#define TG_B_HI 65536
#define TG_B_LO 98304
#define TG_SMEM_BYTES 131072

__global__ __launch_bounds__(256, 1) void proj_tc_kernel(
    const float* __restrict__ gw, const float* __restrict__ gb,
    const float* __restrict__ thw, const float* __restrict__ thb,
    const float* __restrict__ phw, const float* __restrict__ phb)
{
    extern __shared__ char smem[];
    const uint32_t sb = smem_u32(smem);
    const int t = threadIdx.x;
    const int lane = t & 31, w = t >> 5;
    const int b = blockIdx.z;
    const int m0 = blockIdx.y * 128;
    const int n0 = blockIdx.x * 128;

    const float* wsrc;
    const float* bsrc;
    if (m0 == 0)        { wsrc = gw;  bsrc = gb;  }
    else if (m0 == 128) { wsrc = thw; bsrc = thb; }
    else                { wsrc = phw; bsrc = phb; }

    const int frow = lane & 15, fhalf = lane >> 4;
    const int arow = w * 16 + frow;

    float acc[16][4];
#pragma unroll
    for (int nf = 0; nf < 16; nf++)
#pragma unroll
        for (int j = 0; j < 4; j++) acc[nf][j] = 0.0f;

#pragma unroll 1
    for (int k0 = 0; k0 < CIN; k0 += 128) {
        __syncthreads();
        split_tile(sb + TG_A_HI, sb + TG_A_LO, wsrc + k0, CIN);
        load_tile(sb + TG_B_HI, d_xt_hi + (size_t)(b * NN + n0) * CIN + k0, CIN);
        load_tile(sb + TG_B_LO, d_xt_lo + (size_t)(b * NN + n0) * CIN + k0, CIN);
        __syncthreads();

#pragma unroll 1
        for (int kk = 0; kk < 8; kk++) {
            uint32_t ah[4], al[4];
            ldsm4(ah[0], ah[1], ah[2], ah[3], sw_addr(sb + TG_A_HI, arow, kk * 2 + fhalf));
            ldsm4(al[0], al[1], al[2], al[3], sw_addr(sb + TG_A_LO, arow, kk * 2 + fhalf));
#pragma unroll
            for (int np = 0; np < 8; np++) {
                uint32_t bh[4], bl[4];
                ldsm4(bh[0], bh[1], bh[2], bh[3], sw_addr(sb + TG_B_HI, np * 16 + frow, kk * 2 + fhalf));
                ldsm4(bl[0], bl[1], bl[2], bl[3], sw_addr(sb + TG_B_LO, np * 16 + frow, kk * 2 + fhalf));
                mma16816(acc[2 * np],     ah[0], ah[1], ah[2], ah[3], bh[0], bh[2]);
                mma16816(acc[2 * np + 1], ah[0], ah[1], ah[2], ah[3], bh[1], bh[3]);
                mma16816(acc[2 * np],     ah[0], ah[1], ah[2], ah[3], bl[0], bl[2]);
                mma16816(acc[2 * np + 1], ah[0], ah[1], ah[2], ah[3], bl[1], bl[3]);
                mma16816(acc[2 * np],     al[0], al[1], al[2], al[3], bh[0], bh[2]);
                mma16816(acc[2 * np + 1], al[0], al[1], al[2], al[3], bh[1], bh[3]);
            }
        }
    }

    const int rl = w * 16 + (lane >> 2);
    const float bias0 = bsrc[rl];
    const float bias1 = bsrc[rl + 8];
    float* out0 = d_proj + (size_t)(m0 + rl) * (BB * NN) + (size_t)b * NN + n0;
    float* out1 = d_proj + (size_t)(m0 + rl + 8) * (BB * NN) + (size_t)b * NN + n0;
    float s0 = 0.f, q0 = 0.f, s1 = 0.f, q1 = 0.f;
#pragma unroll
    for (int nf = 0; nf < 16; nf++) {
        int n = nf * 8 + (lane & 3) * 2;
        float v00 = acc[nf][0] + bias0, v01 = acc[nf][1] + bias0;
        float v10 = acc[nf][2] + bias1, v11 = acc[nf][3] + bias1;
        *(float2*)(out0 + n) = make_float2(v00, v01);
        *(float2*)(out1 + n) = make_float2(v10, v11);
        s0 += v00 + v01; q0 += v00 * v00 + v01 * v01;
        s1 += v10 + v11; q1 += v10 * v10 + v11 * v11;
    }
    s0 += __shfl_xor_sync(0xffffffffu, s0, 1); s0 += __shfl_xor_sync(0xffffffffu, s0, 2);
    q0 += __shfl_xor_sync(0xffffffffu, q0, 1); q0 += __shfl_xor_sync(0xffffffffu, q0, 2);
    s1 += __shfl_xor_sync(0xffffffffu, s1, 1); s1 += __shfl_xor_sync(0xffffffffu, s1, 2);
    q1 += __shfl_xor_sync(0xffffffffu, q1, 1); q1 += __shfl_xor_sync(0xffffffffu, q1, 2);
    if ((lane & 3) == 0) {
        atomicAdd(&d_psum[m0 + rl], s0);     atomicAdd(&d_psumsq[m0 + rl], q0);
        atomicAdd(&d_psum[m0 + rl + 8], s1); atomicAdd(&d_psumsq[m0 + rl + 8], q1);
    }
}

// ---------------- prep theta/phi/g (BN applied from raw sums) ----------------
__global__ __launch_bounds__(256) void prep_qkg_kernel(
    const float* __restrict__ g_gamma, const float* __restrict__ g_beta,
    const float* __restrict__ th_gamma, const float* __restrict__ th_beta,
    const float* __restrict__ ph_gamma, const float* __restrict__ ph_beta)
{
    __shared__ float tile[32][33];
    __shared__ float sscale[32], sshift[32];
    const int t = threadIdx.x;
    const int tx = t & 31, ty = t >> 5;
    const int sel = blockIdx.z >> 2;      // 0 theta, 1 phi, 2 g
    const int b = blockIdx.z & 3;
    const int c0 = blockIdx.y * 32;
    const int n0 = blockIdx.x * 32;
    const int chbase = (sel == 2) ? 0 : (128 + sel * 128);
    if (t < 32) {
        int ch = chbase + c0 + t;
        float mean = d_psum[ch] * (1.0f / (BB * NN));
        float var = d_psumsq[ch] * (1.0f / (BB * NN)) - mean * mean;
        float gamma, beta;
        if (sel == 0)      { gamma = th_gamma[c0 + t]; beta = th_beta[c0 + t]; }
        else if (sel == 1) { gamma = ph_gamma[c0 + t]; beta = ph_beta[c0 + t]; }
        else               { gamma = g_gamma[c0 + t];  beta = g_beta[c0 + t]; }
        float sc = gamma * rsqrtf(var + BN_EPS);
        sscale[t] = sc;
        sshift[t] = beta - mean * sc;
    }
    __syncthreads();
    if (sel == 2) {
#pragma unroll
        for (int i = 0; i < 4; i++) {
            int cc = ty + i * 8;
            int c = c0 + cc;
            float v = d_proj[(size_t)c * (BB * NN) + (size_t)b * NN + n0 + tx];
            float r = v * sscale[cc] + sshift[cc];
            d_g_hi[(size_t)(b * CI + c) * NN + n0 + tx] = __float2half_rn(r);
        }
        return;
    }
#pragma unroll
    for (int i = 0; i < 4; i++) {
        int cc = ty + i * 8;
        float v = d_proj[(size_t)(chbase + c0 + cc) * (BB * NN) + (size_t)b * NN + n0 + tx];
        tile[cc][tx] = v * sscale[cc] + sshift[cc];
    }
    __syncthreads();
    __half* hi = sel ? d_ph_hi : d_th_hi;
    __half* lo = sel ? d_ph_lo : d_th_lo;
#pragma unroll
    for (int i = 0; i < 4; i++) {
        int n = n0 + ty + i * 8;
        float v = tile[tx][ty + i * 8];
        __half h = __float2half_rn(v);
        __half l = __float2half_rn(v - __half2float(h));
        size_t idx = (size_t)(b * NN + n) * CI + c0 + tx;
        hi[idx] = h;
        lo[idx] = l;
    }
}

// ---------------- Kernel 3: 2-CTA/SM flash attention, 64-key half-tiles ----------------
// 128 threads (4 warps), 64-row q-tile, single-buffered K/G, split-group prefetch.
// Each 128-key tile processed as two 64-key halves: S_h -> softmax update -> exp -> PV_h.
#define A_QLO 0          // 64 x 256B = 16KB
#define A_KHI 16384
#define A_KLO 49152
#define A_GHI 81920
#define ATTN_SMEM_BYTES 114688

__global__ __launch_bounds__(128, 2) void attn_mma_kernel()
{
    extern __shared__ char smem[];
    const uint32_t sb = smem_u32(smem);
    const int tid = threadIdx.x;
    const int lane = tid & 31;
    const int w = tid >> 5;          // 0..3
    const int b = blockIdx.y;
    const int n0 = blockIdx.x * 64;

    const int frow = lane & 15;
    const int fhalf = lane >> 4;
    const int arow = w * 16 + frow;

    // ---- stage Qhi via GHI buffer; Qlo into QLO ----
    load_tile64_a128(sb + A_GHI, d_th_hi + (size_t)(b * NN + n0) * CI, CI);
    load_tile64_a128(sb + A_QLO, d_th_lo + (size_t)(b * NN + n0) * CI, CI);
    CP_COMMIT(); CP_WAIT_ALL(); __syncthreads();
    uint32_t qh[8][4];
#pragma unroll
    for (int kk = 0; kk < 8; kk++)
        ldsm4(qh[kk][0], qh[kk][1], qh[kk][2], qh[kk][3], sw_addr(sb + A_GHI, arow, kk * 2 + fhalf));
    __syncthreads();

    // ---- prologue prefetch: K(0) group, then G(0) group ----
    load_tile128_a128(sb + A_KHI, d_ph_hi + (size_t)(b * NN) * CI, CI);
    load_tile128_a128(sb + A_KLO, d_ph_lo + (size_t)(b * NN) * CI, CI);
    CP_COMMIT();
    load_tile128_a128(sb + A_GHI, d_g_hi + (size_t)b * CI * NN, NN);
    CP_COMMIT();

    float o[16][4];
#pragma unroll
    for (int nf = 0; nf < 16; nf++)
#pragma unroll
        for (int j = 0; j < 4; j++) o[nf][j] = 0.0f;
    float mr0 = -INFINITY, mr1 = -INFINITY, lr0 = 0.0f, lr1 = 0.0f;

#pragma unroll 1
    for (int t = 0; t < NTILES; t++) {
        // K(t) ready (G(t) may still be in flight)
        CP_WAIT_1();
        __syncthreads();

#pragma unroll 1
        for (int hh = 0; hh < 2; hh++) {
            // ---- S_h = Qh*Kh^T + Qh*Kl^T + Ql*Kh^T  (64-key half) ----
            float s[8][4];
#pragma unroll
            for (int nf = 0; nf < 8; nf++)
#pragma unroll
                for (int j = 0; j < 4; j++) s[nf][j] = 0.0f;

#pragma unroll 1
            for (int kk = 0; kk < 8; kk++) {
                uint32_t ql[4];
                ldsm4(ql[0], ql[1], ql[2], ql[3], sw_addr(sb + A_QLO, arow, kk * 2 + fhalf));
#pragma unroll
                for (int np = 0; np < 4; np++) {
                    const int krow = hh * 64 + np * 16 + frow;
                    uint32_t kh[4], kl[4];
                    ldsm4(kh[0], kh[1], kh[2], kh[3], sw_addr(sb + A_KHI, krow, kk * 2 + fhalf));
                    ldsm4(kl[0], kl[1], kl[2], kl[3], sw_addr(sb + A_KLO, krow, kk * 2 + fhalf));
                    mma16816(s[2 * np],     qh[kk][0], qh[kk][1], qh[kk][2], qh[kk][3], kh[0], kh[2]);
                    mma16816(s[2 * np + 1], qh[kk][0], qh[kk][1], qh[kk][2], qh[kk][3], kh[1], kh[3]);
                    mma16816(s[2 * np],     qh[kk][0], qh[kk][1], qh[kk][2], qh[kk][3], kl[0], kl[2]);
                    mma16816(s[2 * np + 1], qh[kk][0], qh[kk][1], qh[kk][2], qh[kk][3], kl[1], kl[3]);
                    mma16816(s[2 * np],     ql[0], ql[1], ql[2], ql[3], kh[0], kh[2]);
                    mma16816(s[2 * np + 1], ql[0], ql[1], ql[2], ql[3], kh[1], kh[3]);
                }
            }

            if (hh == 1) {
                // K fully consumed -> prefetch K(t+1) (covered by softmax+PV below)
                __syncthreads();
                if (t + 1 < NTILES) {
                    const int m1 = (t + 1) * 128;
                    load_tile128_a128(sb + A_KHI, d_ph_hi + (size_t)(b * NN + m1) * CI, CI);
                    load_tile128_a128(sb + A_KLO, d_ph_lo + (size_t)(b * NN + m1) * CI, CI);
                    CP_COMMIT();
                }
            }

            // ---- softmax update over this half ----
            float tm0 = -INFINITY, tm1 = -INFINITY;
#pragma unroll
            for (int nf = 0; nf < 8; nf++) {
                tm0 = fmaxf(tm0, fmaxf(s[nf][0], s[nf][1]));
                tm1 = fmaxf(tm1, fmaxf(s[nf][2], s[nf][3]));
            }
            tm0 = fmaxf(tm0, __shfl_xor_sync(0xffffffffu, tm0, 1));
            tm0 = fmaxf(tm0, __shfl_xor_sync(0xffffffffu, tm0, 2));
            tm1 = fmaxf(tm1, __shfl_xor_sync(0xffffffffu, tm1, 1));
            tm1 = fmaxf(tm1, __shfl_xor_sync(0xffffffffu, tm1, 2));
            float mn0 = fmaxf(mr0, tm0), mn1 = fmaxf(mr1, tm1);
            float c0 = __expf(mr0 - mn0), c1 = __expf(mr1 - mn1);
            mr0 = mn0; mr1 = mn1;
#pragma unroll
            for (int nf = 0; nf < 16; nf++) {
                o[nf][0] *= c0; o[nf][1] *= c0; o[nf][2] *= c1; o[nf][3] *= c1;
            }

            // G(t) must be fully landed before the first PV of this tile.
            // At this point G(t) is the ONLY outstanding group, so wait_group 0.
            if (hh == 0) {
                CP_WAIT_ALL();
                __syncthreads();
            }

            // ---- exp + pack ----
            uint32_t ph[8][2];
            float rs0 = 0.0f, rs1 = 0.0f;
#pragma unroll
            for (int nf = 0; nf < 8; nf++) {
                float p0 = __expf(s[nf][0] - mn0);
                float p1 = __expf(s[nf][1] - mn0);
                float p2 = __expf(s[nf][2] - mn1);
                float p3 = __expf(s[nf][3] - mn1);
                rs0 += p0 + p1; rs1 += p2 + p3;
                ph[nf][0] = packh2(__float2half_rn(p0), __float2half_rn(p1));
                ph[nf][1] = packh2(__float2half_rn(p2), __float2half_rn(p3));
            }
            rs0 += __shfl_xor_sync(0xffffffffu, rs0, 1);
            rs0 += __shfl_xor_sync(0xffffffffu, rs0, 2);
            rs1 += __shfl_xor_sync(0xffffffffu, rs1, 1);
            rs1 += __shfl_xor_sync(0xffffffffu, rs1, 2);
            lr0 = lr0 * c0 + rs0;
            lr1 = lr1 * c1 + rs1;

            // ---- PV_h: O += P_h * Ghi^T (contraction over this half's 64 keys) ----
#pragma unroll
            for (int k2 = 0; k2 < 4; k2++) {
                const int kk = hh * 4 + k2;
                uint32_t a0 = ph[2 * k2][0], a1 = ph[2 * k2][1];
                uint32_t a2 = ph[2 * k2 + 1][0], a3 = ph[2 * k2 + 1][1];
#pragma unroll
                for (int np = 0; np < 8; np++) {
                    uint32_t gh[4];
                    ldsm4(gh[0], gh[1], gh[2], gh[3], sw_addr(sb + A_GHI, np * 16 + frow, kk * 2 + fhalf));
                    mma16816(o[2 * np],     a0, a1, a2, a3, gh[0], gh[2]);
                    mma16816(o[2 * np + 1], a0, a1, a2, a3, gh[1], gh[3]);
                }
            }
        }

        // G fully consumed -> prefetch G(t+1) (covered by next tile's S)
        __syncthreads();
        if (t + 1 < NTILES) {
            const int m1 = (t + 1) * 128;
            load_tile128_a128(sb + A_GHI, d_g_hi + (size_t)b * CI * NN + m1, NN);
            CP_COMMIT();
        }
    }

    // epilogue: y = O / l, split hi/lo, store directly as [b][n][c] fp16
    const float inv0 = 1.0f / lr0, inv1 = 1.0f / lr1;
    const int q0 = n0 + w * 16 + (lane >> 2);
    __half* yh0 = d_y_hi + (size_t)(b * NN + q0) * CI;
    __half* yl0 = d_y_lo + (size_t)(b * NN + q0) * CI;
    __half* yh1 = d_y_hi + (size_t)(b * NN + q0 + 8) * CI;
    __half* yl1 = d_y_lo + (size_t)(b * NN + q0 + 8) * CI;
#pragma unroll
    for (int nf = 0; nf < 16; nf++) {
        int c = nf * 8 + (lane & 3) * 2;
        float v0 = o[nf][0] * inv0, v1 = o[nf][1] * inv0;
        float v2 = o[nf][2] * inv1, v3 = o[nf][3] * inv1;
        __half h0 = __float2half_rn(v0), h1 = __float2half_rn(v1);
        __half h2 = __float2half_rn(v2), h3 = __float2half_rn(v3);
        *(__half2*)(yh0 + c) = __halves2half2(h0, h1);
        *(__half2*)(yl0 + c) = __halves2half2(__float2half_rn(v0 - __half2float(h0)),
                                              __float2half_rn(v1 - __half2float(h1)));
        *(__half2*)(yh1 + c) = __halves2half2(h2, h3);
        *(__half2*)(yl1 + c) = __halves2half2(__float2half_rn(v2 - __half2float(h2)),
                                              __float2half_rn(v3 - __half2float(h3)));
    }
}

// ---------------- Kernel 4: tensor-core W GEMM + bias + residual + fused stats ----------------
__global__ __launch_bounds__(256, 1) void wgemm_tc_kernel(
    const float* __restrict__ x,
    const float* __restrict__ Ww, const float* __restrict__ Wb)
{
    extern __shared__ char smem[];
    const uint32_t sb = smem_u32(smem);
    const int t = threadIdx.x;
    const int lane = t & 31, w = t >> 5;
    const int b = blockIdx.z;
    const int o0 = blockIdx.y * 128;
    const int n0 = blockIdx.x * 128;

    const int frow = lane & 15, fhalf = lane >> 4;
    const int arow = w * 16 + frow;

    split_tile(sb + TG_A_HI, sb + TG_A_LO, Ww + (size_t)o0 * CI, CI);
    load_tile(sb + TG_B_HI, d_y_hi + (size_t)(b * NN + n0) * CI, CI);
    load_tile(sb + TG_B_LO, d_y_lo + (size_t)(b * NN + n0) * CI, CI);
    __syncthreads();

    float acc[16][4];
#pragma unroll
    for (int nf = 0; nf < 16; nf++)
#pragma unroll
        for (int j = 0; j < 4; j++) acc[nf][j] = 0.0f;

#pragma unroll 1
    for (int kk = 0; kk < 8; kk++) {
        uint32_t ah[4], al[4];
        ldsm4(ah[0], ah[1], ah[2], ah[3], sw_addr(sb + TG_A_HI, arow, kk * 2 + fhalf));
        ldsm4(al[0], al[1], al[2], al[3], sw_addr(sb + TG_A_LO, arow, kk * 2 + fhalf));
#pragma unroll
        for (int np = 0; np < 8; np++) {
            uint32_t bh[4], bl[4];
            ldsm4(bh[0], bh[1], bh[2], bh[3], sw_addr(sb + TG_B_HI, np * 16 + frow, kk * 2 + fhalf));
            ldsm4(bl[0], bl[1], bl[2], bl[3], sw_addr(sb + TG_B_LO, np * 16 + frow, kk * 2 + fhalf));
            mma16816(acc[2 * np],     ah[0], ah[1], ah[2], ah[3], bh[0], bh[2]);
            mma16816(acc[2 * np + 1], ah[0], ah[1], ah[2], ah[3], bh[1], bh[3]);
            mma16816(acc[2 * np],     ah[0], ah[1], ah[2], ah[3], bl[0], bl[2]);
            mma16816(acc[2 * np + 1], ah[0], ah[1], ah[2], ah[3], bl[1], bl[3]);
            mma16816(acc[2 * np],     al[0], al[1], al[2], al[3], bh[0], bh[2]);
            mma16816(acc[2 * np + 1], al[0], al[1], al[2], al[3], bh[1], bh[3]);
        }
    }

    const int rl = o0 + w * 16 + (lane >> 2);
    const float bias0 = Wb[rl], bias1 = Wb[rl + 8];
    const float* xr0 = x + (size_t)(b * COUT + rl) * NN + n0;
    const float* xr1 = x + (size_t)(b * COUT + rl + 8) * NN + n0;
    float* z0 = d_z + (size_t)rl * (BB * NN) + (size_t)b * NN + n0;
    float* z1 = d_z + (size_t)(rl + 8) * (BB * NN) + (size_t)b * NN + n0;
    float s0 = 0.f, q0 = 0.f, s1 = 0.f, q1 = 0.f;
#pragma unroll
    for (int nf = 0; nf < 16; nf++) {
        int n = nf * 8 + (lane & 3) * 2;
        float2 xa = *(const float2*)(xr0 + n);
        float2 xb = *(const float2*)(xr1 + n);
        float v00 = acc[nf][0] + bias0 + xa.x, v01 = acc[nf][1] + bias0 + xa.y;
        float v10 = acc[nf][2] + bias1 + xb.x, v11 = acc[nf][3] + bias1 + xb.y;
        *(float2*)(z0 + n) = make_float2(v00, v01);
        *(float2*)(z1 + n) = make_float2(v10, v11);
        s0 += v00 + v01; q0 += v00 * v00 + v01 * v01;
        s1 += v10 + v11; q1 += v10 * v10 + v11 * v11;
    }
    s0 += __shfl_xor_sync(0xffffffffu, s0, 1); s0 += __shfl_xor_sync(0xffffffffu, s0, 2);
    q0 += __shfl_xor_sync(0xffffffffu, q0, 1); q0 += __shfl_xor_sync(0xffffffffu, q0, 2);
    s1 += __shfl_xor_sync(0xffffffffu, s1, 1); s1 += __shfl_xor_sync(0xffffffffu, s1, 2);
    q1 += __shfl_xor_sync(0xffffffffu, q1, 1); q1 += __shfl_xor_sync(0xffffffffu, q1, 2);
    if ((lane & 3) == 0) {
        atomicAdd(&d_zsum[rl], s0);     atomicAdd(&d_zsumsq[rl], q0);
        atomicAdd(&d_zsum[rl + 8], s1); atomicAdd(&d_zsumsq[rl + 8], q1);
    }
}

// ---------------- final normalize (BN finalize fused per-thread) ----------------
__global__ __launch_bounds__(256) void finalize_kernel(
    const float* __restrict__ bn_gamma, const float* __restrict__ bn_beta,
    float* __restrict__ out)
{
    int idx = blockIdx.x * 256 + threadIdx.x;
    int o = idx >> 14;
    int rem = idx & 16383;
    int b = rem >> 12;
    int n = rem & 4095;
    float mean = d_zsum[o] * (1.0f / (BB * NN));
    float var = d_zsumsq[o] * (1.0f / (BB * NN)) - mean * mean;
    float sc = bn_gamma[o] * rsqrtf(var + BN_EPS);
    float sh = bn_beta[o] - mean * sc;
    out[(b * COUT + o) * NN + n] = d_z[idx] * sc + sh;
}

// ---------------- host launcher ----------------
extern "C" void kernel_launch(void* const* d_in, const int* in_sizes, int n_in,
                              void* d_out, int out_size)
{
    const float* x        = (const float*)d_in[0];
    const float* g_w      = (const float*)d_in[1];
    const float* g_b      = (const float*)d_in[2];
    const float* g_gamma  = (const float*)d_in[3];
    const float* g_beta   = (const float*)d_in[4];
    const float* th_w     = (const float*)d_in[5];
    const float* th_b     = (const float*)d_in[6];
    const float* th_gamma = (const float*)d_in[7];
    const float* th_beta  = (const float*)d_in[8];
    const float* ph_w     = (const float*)d_in[9];
    const float* ph_b     = (const float*)d_in[10];
    const float* ph_gamma = (const float*)d_in[11];
    const float* ph_beta  = (const float*)d_in[12];
    const float* W_w      = (const float*)d_in[13];
    const float* W_b      = (const float*)d_in[14];
    const float* bn_gamma = (const float*)d_in[15];
    const float* bn_beta  = (const float*)d_in[16];
    float* out = (float*)d_out;

    cudaFuncSetAttribute(proj_tc_kernel, cudaFuncAttributeMaxDynamicSharedMemorySize, TG_SMEM_BYTES);
    cudaFuncSetAttribute(wgemm_tc_kernel, cudaFuncAttributeMaxDynamicSharedMemorySize, TG_SMEM_BYTES);
    cudaFuncSetAttribute(attn_mma_kernel, cudaFuncAttributeMaxDynamicSharedMemorySize, ATTN_SMEM_BYTES);

    prep_xt_kernel<<<dim3(NN / 32, CIN / 32, BB), 256>>>(x);
    proj_tc_kernel<<<dim3(NN / 128, CP / 128, BB), 256, TG_SMEM_BYTES>>>(
        g_w, g_b, th_w, th_b, ph_w, ph_b);
    prep_qkg_kernel<<<dim3(NN / 32, CI / 32, BB * 3), 256>>>(
        g_gamma, g_beta, th_gamma, th_beta, ph_gamma, ph_beta);
    attn_mma_kernel<<<dim3(NN / 64, BB), 128, ATTN_SMEM_BYTES>>>();
    wgemm_tc_kernel<<<dim3(NN / 128, COUT / 128, BB), 256, TG_SMEM_BYTES>>>(x, W_w, W_b);
    finalize_kernel<<<(COUT * BB * NN) / 256, 256>>>(bn_gamma, bn_beta, out);
}

// round 14
// speedup vs baseline: 1.1101x; 1.1101x over previous
#include <cuda_runtime.h>
#include <cuda_fp16.h>
#include <math.h>
#include <stdint.h>

// Problem constants
#define BB 4
#define CIN 256
#define CI 128
#define NN 4096          // H*W = 64*64
#define CP 384           // 3*CI projection channels
#define COUT 256
#define BN_EPS 1e-5f
#define NTILES 32        // NN / 128 key tiles

// Scratch (static device globals; allocation APIs are forbidden)
__device__ float d_proj[CP * BB * NN];     // [m][b][n]
__device__ float d_psum[CP];
__device__ float d_psumsq[CP];
__device__ float d_z[COUT * BB * NN];      // [o][b][n]
__device__ float d_zsum[COUT];
__device__ float d_zsumsq[COUT];

// fp16 hi/lo split operands
__device__ __half d_xt_hi[BB * NN * CIN];  // x^T      [b][n][c]
__device__ __half d_xt_lo[BB * NN * CIN];
__device__ __half d_th_hi[BB * NN * CI];   // theta^T  [b][n][c]
__device__ __half d_th_lo[BB * NN * CI];
__device__ __half d_ph_hi[BB * NN * CI];   // phi^T    [b][n][c]
__device__ __half d_ph_lo[BB * NN * CI];
__device__ __half d_g_hi[BB * CI * NN];    // g        [b][c][n]
__device__ __half d_y_hi[BB * NN * CI];    // y^T      [b][n][c]
__device__ __half d_y_lo[BB * NN * CI];

// ======================= helpers =======================
__device__ __forceinline__ uint32_t smem_u32(const void* p) {
    uint32_t a;
    asm("{ .reg .u64 t; cvta.to.shared.u64 t, %1; cvt.u32.u64 %0, t; }" : "=r"(a) : "l"(p));
    return a;
}

__device__ __forceinline__ void ldsm4(uint32_t& r0, uint32_t& r1, uint32_t& r2, uint32_t& r3,
                                      uint32_t addr) {
    asm volatile("ldmatrix.sync.aligned.m8n8.x4.shared.b16 {%0,%1,%2,%3}, [%4];"
                 : "=r"(r0), "=r"(r1), "=r"(r2), "=r"(r3) : "r"(addr));
}

__device__ __forceinline__ void mma16816(float* d, uint32_t a0, uint32_t a1, uint32_t a2, uint32_t a3,
                                         uint32_t b0, uint32_t b1) {
    asm volatile(
        "mma.sync.aligned.m16n8k16.row.col.f32.f16.f16.f32 "
        "{%0,%1,%2,%3}, {%4,%5,%6,%7}, {%8,%9}, {%0,%1,%2,%3};"
        : "+f"(d[0]), "+f"(d[1]), "+f"(d[2]), "+f"(d[3])
        : "r"(a0), "r"(a1), "r"(a2), "r"(a3), "r"(b0), "r"(b1));
}

__device__ __forceinline__ uint32_t sw_addr(uint32_t base, int row, int chunk) {
    return base + (uint32_t)row * 256u + (uint32_t)((chunk ^ (row & 7)) << 4);
}

__device__ __forceinline__ uint32_t packh2(__half a, __half b) {
    __half2 h = __halves2half2(a, b);
    return *(uint32_t*)&h;
}

__device__ __forceinline__ void cpasync16(uint32_t dst, const void* src) {
    asm volatile("cp.async.cg.shared.global [%0], [%1], 16;" :: "r"(dst), "l"(src));
}
#define CP_COMMIT()   asm volatile("cp.async.commit_group;" ::: "memory")
#define CP_WAIT_ALL() asm volatile("cp.async.wait_group 0;" ::: "memory")
#define CP_WAIT_1()   asm volatile("cp.async.wait_group 1;" ::: "memory")

// 256-thread cooperative tile loaders (for GEMM kernels)
__device__ __forceinline__ void load_tile(uint32_t dst, const __half* __restrict__ src,
                                          int row_stride) {
    const int t = threadIdx.x;
#pragma unroll
    for (int i = 0; i < 8; i++) {
        int cid = i * 256 + t;
        int row = cid >> 4, c = cid & 15;
        uint4 v = *(const uint4*)(src + (size_t)row * row_stride + c * 8);
        uint32_t a = sw_addr(dst, row, c);
        asm volatile("st.shared.v4.b32 [%0], {%1, %2, %3, %4};"
                     :: "r"(a), "r"(v.x), "r"(v.y), "r"(v.z), "r"(v.w));
    }
}

// 128-thread async loaders (attention)
__device__ __forceinline__ void load_tile128_a128(uint32_t dst, const __half* __restrict__ src,
                                                  int row_stride) {
    const int t = threadIdx.x;
#pragma unroll
    for (int i = 0; i < 16; i++) {
        int cid = i * 128 + t;
        int row = cid >> 4, c = cid & 15;
        cpasync16(sw_addr(dst, row, c), src + (size_t)row * row_stride + c * 8);
    }
}
__device__ __forceinline__ void load_tile64_a128(uint32_t dst, const __half* __restrict__ src,
                                                 int row_stride) {
    const int t = threadIdx.x;
#pragma unroll
    for (int i = 0; i < 8; i++) {
        int cid = i * 128 + t;
        int row = cid >> 4, c = cid & 15;
        cpasync16(sw_addr(dst, row, c), src + (size_t)row * row_stride + c * 8);
    }
}

__device__ __forceinline__ void split_tile(uint32_t dhi, uint32_t dlo,
                                           const float* __restrict__ src, int row_stride) {
    const int t = threadIdx.x;
#pragma unroll
    for (int i = 0; i < 8; i++) {
        int cid = i * 256 + t;
        int row = cid >> 4, c = cid & 15;
        const float* p = src + (size_t)row * row_stride + c * 8;
        float4 v0 = *(const float4*)p;
        float4 v1 = *(const float4*)(p + 4);
        float e[8] = {v0.x, v0.y, v0.z, v0.w, v1.x, v1.y, v1.z, v1.w};
        __half h[8], l[8];
#pragma unroll
        for (int j = 0; j < 8; j++) {
            h[j] = __float2half_rn(e[j]);
            l[j] = __float2half_rn(e[j] - __half2float(h[j]));
        }
        asm volatile("st.shared.v4.b32 [%0], {%1, %2, %3, %4};"
                     :: "r"(sw_addr(dhi, row, c)), "r"(packh2(h[0], h[1])), "r"(packh2(h[2], h[3])),
                        "r"(packh2(h[4], h[5])), "r"(packh2(h[6], h[7])));
        asm volatile("st.shared.v4.b32 [%0], {%1, %2, %3, %4};"
                     :: "r"(sw_addr(dlo, row, c)), "r"(packh2(l[0], l[1])), "r"(packh2(l[2], l[3])),
                        "r"(packh2(l[4], l[5])), "r"(packh2(l[6], l[7])));
    }
}

// ---------------- Kernel 0: transpose+split x (+ zero stats in block 0) ----------------
__global__ __launch_bounds__(256) void prep_xt_kernel(const float* __restrict__ x)
{
    __shared__ float tile[32][33];
    const int t = threadIdx.x;
    if (blockIdx.x == 0 && blockIdx.y == 0 && blockIdx.z == 0) {
        for (int i = t; i < CP; i += 256) { d_psum[i] = 0.0f; d_psumsq[i] = 0.0f; }
        if (t < COUT) { d_zsum[t] = 0.0f; d_zsumsq[t] = 0.0f; }
    }
    const int tx = t & 31, ty = t >> 5;
    const int b = blockIdx.z;
    const int c0 = blockIdx.y * 32;
    const int n0 = blockIdx.x * 32;
#pragma unroll
    for (int i = 0; i < 4; i++) {
        int c = c0 + ty + i * 8;
        tile[ty + i * 8][tx] = x[(size_t)(b * CIN + c) * NN + n0 + tx];
    }
    __syncthreads();
#pragma unroll
    for (int i = 0; i < 4; i++) {
        int n = n0 + ty + i * 8;
        float v = tile[tx][ty + i * 8];
        __half h = __float2half_rn(v);
        __half l = __float2half_rn(v - __half2float(h));
        size_t idx = (size_t)(b * NN + n) * CIN + c0 + tx;
        d_xt_hi[idx] = h;
        d_xt_lo[idx] = l;
    }
}

// ---------------- Kernel 1: tensor-core projection GEMM + fused stats ----------------
#define TG_A_HI 0
#define TG_A_LO 32768
#define TG_B_HI 65536
#define TG_B_LO 98304
#define TG_SMEM_BYTES 131072

__global__ __launch_bounds__(256, 1) void proj_tc_kernel(
    const float* __restrict__ gw, const float* __restrict__ gb,
    const float* __restrict__ thw, const float* __restrict__ thb,
    const float* __restrict__ phw, const float* __restrict__ phb)
{
    extern __shared__ char smem[];
    const uint32_t sb = smem_u32(smem);
    const int t = threadIdx.x;
    const int lane = t & 31, w = t >> 5;
    const int b = blockIdx.z;
    const int m0 = blockIdx.y * 128;
    const int n0 = blockIdx.x * 128;

    const float* wsrc;
    const float* bsrc;
    if (m0 == 0)        { wsrc = gw;  bsrc = gb;  }
    else if (m0 == 128) { wsrc = thw; bsrc = thb; }
    else                { wsrc = phw; bsrc = phb; }

    const int frow = lane & 15, fhalf = lane >> 4;
    const int arow = w * 16 + frow;

    float acc[16][4];
#pragma unroll
    for (int nf = 0; nf < 16; nf++)
#pragma unroll
        for (int j = 0; j < 4; j++) acc[nf][j] = 0.0f;

#pragma unroll 1
    for (int k0 = 0; k0 < CIN; k0 += 128) {
        __syncthreads();
        split_tile(sb + TG_A_HI, sb + TG_A_LO, wsrc + k0, CIN);
        load_tile(sb + TG_B_HI, d_xt_hi + (size_t)(b * NN + n0) * CIN + k0, CIN);
        load_tile(sb + TG_B_LO, d_xt_lo + (size_t)(b * NN + n0) * CIN + k0, CIN);
        __syncthreads();

#pragma unroll 1
        for (int kk = 0; kk < 8; kk++) {
            uint32_t ah[4], al[4];
            ldsm4(ah[0], ah[1], ah[2], ah[3], sw_addr(sb + TG_A_HI, arow, kk * 2 + fhalf));
            ldsm4(al[0], al[1], al[2], al[3], sw_addr(sb + TG_A_LO, arow, kk * 2 + fhalf));
#pragma unroll
            for (int np = 0; np < 8; np++) {
                uint32_t bh[4], bl[4];
                ldsm4(bh[0], bh[1], bh[2], bh[3], sw_addr(sb + TG_B_HI, np * 16 + frow, kk * 2 + fhalf));
                ldsm4(bl[0], bl[1], bl[2], bl[3], sw_addr(sb + TG_B_LO, np * 16 + frow, kk * 2 + fhalf));
                mma16816(acc[2 * np],     ah[0], ah[1], ah[2], ah[3], bh[0], bh[2]);
                mma16816(acc[2 * np + 1], ah[0], ah[1], ah[2], ah[3], bh[1], bh[3]);
                mma16816(acc[2 * np],     ah[0], ah[1], ah[2], ah[3], bl[0], bl[2]);
                mma16816(acc[2 * np + 1], ah[0], ah[1], ah[2], ah[3], bl[1], bl[3]);
                mma16816(acc[2 * np],     al[0], al[1], al[2], al[3], bh[0], bh[2]);
                mma16816(acc[2 * np + 1], al[0], al[1], al[2], al[3], bh[1], bh[3]);
            }
        }
    }

    const int rl = w * 16 + (lane >> 2);
    const float bias0 = bsrc[rl];
    const float bias1 = bsrc[rl + 8];
    float* out0 = d_proj + (size_t)(m0 + rl) * (BB * NN) + (size_t)b * NN + n0;
    float* out1 = d_proj + (size_t)(m0 + rl + 8) * (BB * NN) + (size_t)b * NN + n0;
    float s0 = 0.f, q0 = 0.f, s1 = 0.f, q1 = 0.f;
#pragma unroll
    for (int nf = 0; nf < 16; nf++) {
        int n = nf * 8 + (lane & 3) * 2;
        float v00 = acc[nf][0] + bias0, v01 = acc[nf][1] + bias0;
        float v10 = acc[nf][2] + bias1, v11 = acc[nf][3] + bias1;
        *(float2*)(out0 + n) = make_float2(v00, v01);
        *(float2*)(out1 + n) = make_float2(v10, v11);
        s0 += v00 + v01; q0 += v00 * v00 + v01 * v01;
        s1 += v10 + v11; q1 += v10 * v10 + v11 * v11;
    }
    s0 += __shfl_xor_sync(0xffffffffu, s0, 1); s0 += __shfl_xor_sync(0xffffffffu, s0, 2);
    q0 += __shfl_xor_sync(0xffffffffu, q0, 1); q0 += __shfl_xor_sync(0xffffffffu, q0, 2);
    s1 += __shfl_xor_sync(0xffffffffu, s1, 1); s1 += __shfl_xor_sync(0xffffffffu, s1, 2);
    q1 += __shfl_xor_sync(0xffffffffu, q1, 1); q1 += __shfl_xor_sync(0xffffffffu, q1, 2);
    if ((lane & 3) == 0) {
        atomicAdd(&d_psum[m0 + rl], s0);     atomicAdd(&d_psumsq[m0 + rl], q0);
        atomicAdd(&d_psum[m0 + rl + 8], s1); atomicAdd(&d_psumsq[m0 + rl + 8], q1);
    }
}

// ---------------- prep theta/phi/g (BN applied from raw sums) ----------------
__global__ __launch_bounds__(256) void prep_qkg_kernel(
    const float* __restrict__ g_gamma, const float* __restrict__ g_beta,
    const float* __restrict__ th_gamma, const float* __restrict__ th_beta,
    const float* __restrict__ ph_gamma, const float* __restrict__ ph_beta)
{
    __shared__ float tile[32][33];
    __shared__ float sscale[32], sshift[32];
    const int t = threadIdx.x;
    const int tx = t & 31, ty = t >> 5;
    const int sel = blockIdx.z >> 2;      // 0 theta, 1 phi, 2 g
    const int b = blockIdx.z & 3;
    const int c0 = blockIdx.y * 32;
    const int n0 = blockIdx.x * 32;
    const int chbase = (sel == 2) ? 0 : (128 + sel * 128);
    if (t < 32) {
        int ch = chbase + c0 + t;
        float mean = d_psum[ch] * (1.0f / (BB * NN));
        float var = d_psumsq[ch] * (1.0f / (BB * NN)) - mean * mean;
        float gamma, beta;
        if (sel == 0)      { gamma = th_gamma[c0 + t]; beta = th_beta[c0 + t]; }
        else if (sel == 1) { gamma = ph_gamma[c0 + t]; beta = ph_beta[c0 + t]; }
        else               { gamma = g_gamma[c0 + t];  beta = g_beta[c0 + t]; }
        float sc = gamma * rsqrtf(var + BN_EPS);
        sscale[t] = sc;
        sshift[t] = beta - mean * sc;
    }
    __syncthreads();
    if (sel == 2) {
#pragma unroll
        for (int i = 0; i < 4; i++) {
            int cc = ty + i * 8;
            int c = c0 + cc;
            float v = d_proj[(size_t)c * (BB * NN) + (size_t)b * NN + n0 + tx];
            float r = v * sscale[cc] + sshift[cc];
            d_g_hi[(size_t)(b * CI + c) * NN + n0 + tx] = __float2half_rn(r);
        }
        return;
    }
#pragma unroll
    for (int i = 0; i < 4; i++) {
        int cc = ty + i * 8;
        float v = d_proj[(size_t)(chbase + c0 + cc) * (BB * NN) + (size_t)b * NN + n0 + tx];
        tile[cc][tx] = v * sscale[cc] + sshift[cc];
    }
    __syncthreads();
    __half* hi = sel ? d_ph_hi : d_th_hi;
    __half* lo = sel ? d_ph_lo : d_th_lo;
#pragma unroll
    for (int i = 0; i < 4; i++) {
        int n = n0 + ty + i * 8;
        float v = tile[tx][ty + i * 8];
        __half h = __float2half_rn(v);
        __half l = __float2half_rn(v - __half2float(h));
        size_t idx = (size_t)(b * NN + n) * CI + c0 + tx;
        hi[idx] = h;
        lo[idx] = l;
    }
}

// ---------------- Kernel 3: 2-CTA/SM desynced flash attention (R11 config) ----------------
// 128 threads (4 warps), 64-row q-tile, single-buffered K/G with split-group prefetch.
// Grid (NN/64, BB) = 256 CTAs, 2/SM -> two independent barrier domains per SM.
#define A_QLO 0          // 64 x 256B = 16KB
#define A_KHI 16384
#define A_KLO 49152
#define A_GHI 81920
#define ATTN_SMEM_BYTES 114688

__global__ __launch_bounds__(128, 2) void attn_mma_kernel()
{
    extern __shared__ char smem[];
    const uint32_t sb = smem_u32(smem);
    const int tid = threadIdx.x;
    const int lane = tid & 31;
    const int w = tid >> 5;          // 0..3
    const int b = blockIdx.y;
    const int n0 = blockIdx.x * 64;

    const int frow = lane & 15;
    const int fhalf = lane >> 4;
    const int arow = w * 16 + frow;

    // ---- stage Qhi via GHI buffer; Qlo into QLO ----
    load_tile64_a128(sb + A_GHI, d_th_hi + (size_t)(b * NN + n0) * CI, CI);
    load_tile64_a128(sb + A_QLO, d_th_lo + (size_t)(b * NN + n0) * CI, CI);
    CP_COMMIT(); CP_WAIT_ALL(); __syncthreads();
    uint32_t qh[8][4];
#pragma unroll
    for (int kk = 0; kk < 8; kk++)
        ldsm4(qh[kk][0], qh[kk][1], qh[kk][2], qh[kk][3], sw_addr(sb + A_GHI, arow, kk * 2 + fhalf));
    __syncthreads();

    // precomputed loop-invariant Qlo ldsm addresses (one per kk)
    uint32_t qlo_ad[8];
#pragma unroll
    for (int kk = 0; kk < 8; kk++) qlo_ad[kk] = sw_addr(sb + A_QLO, arow, kk * 2 + fhalf);

    // ---- prologue prefetch: K(0) group, then G(0) group ----
    load_tile128_a128(sb + A_KHI, d_ph_hi + (size_t)(b * NN) * CI, CI);
    load_tile128_a128(sb + A_KLO, d_ph_lo + (size_t)(b * NN) * CI, CI);
    CP_COMMIT();
    load_tile128_a128(sb + A_GHI, d_g_hi + (size_t)b * CI * NN, NN);
    CP_COMMIT();

    float o[16][4];
#pragma unroll
    for (int nf = 0; nf < 16; nf++)
#pragma unroll
        for (int j = 0; j < 4; j++) o[nf][j] = 0.0f;
    float mr0 = -INFINITY, mr1 = -INFINITY, lr0 = 0.0f, lr1 = 0.0f;

#pragma unroll 1
    for (int t = 0; t < NTILES; t++) {
        // K(t) ready (G(t) may still be in flight)
        CP_WAIT_1();
        __syncthreads();

        // ---- S = Qh*Kh^T + Qh*Kl^T + Ql*Kh^T ----
        float s[16][4];
#pragma unroll
        for (int nf = 0; nf < 16; nf++)
#pragma unroll
            for (int j = 0; j < 4; j++) s[nf][j] = 0.0f;

#pragma unroll 1
        for (int kk = 0; kk < 8; kk++) {
            uint32_t ql[4];
            ldsm4(ql[0], ql[1], ql[2], ql[3], qlo_ad[kk]);
#pragma unroll
            for (int np = 0; np < 8; np++) {
                uint32_t kh[4], kl[4];
                ldsm4(kh[0], kh[1], kh[2], kh[3], sw_addr(sb + A_KHI, np * 16 + frow, kk * 2 + fhalf));
                ldsm4(kl[0], kl[1], kl[2], kl[3], sw_addr(sb + A_KLO, np * 16 + frow, kk * 2 + fhalf));
                mma16816(s[2 * np],     qh[kk][0], qh[kk][1], qh[kk][2], qh[kk][3], kh[0], kh[2]);
                mma16816(s[2 * np + 1], qh[kk][0], qh[kk][1], qh[kk][2], qh[kk][3], kh[1], kh[3]);
                mma16816(s[2 * np],     qh[kk][0], qh[kk][1], qh[kk][2], qh[kk][3], kl[0], kl[2]);
                mma16816(s[2 * np + 1], qh[kk][0], qh[kk][1], qh[kk][2], qh[kk][3], kl[1], kl[3]);
                mma16816(s[2 * np],     ql[0], ql[1], ql[2], ql[3], kh[0], kh[2]);
                mma16816(s[2 * np + 1], ql[0], ql[1], ql[2], ql[3], kh[1], kh[3]);
            }
        }

        // K buffers free -> prefetch K(t+1) (covered by softmax+PV below)
        __syncthreads();
        if (t + 1 < NTILES) {
            const int m1 = (t + 1) * 128;
            load_tile128_a128(sb + A_KHI, d_ph_hi + (size_t)(b * NN + m1) * CI, CI);
            load_tile128_a128(sb + A_KLO, d_ph_lo + (size_t)(b * NN + m1) * CI, CI);
            CP_COMMIT();
        }

        // ---- softmax max/rescale (register-only; overlaps G(t) arrival) ----
        float tm0 = -INFINITY, tm1 = -INFINITY;
#pragma unroll
        for (int nf = 0; nf < 16; nf++) {
            tm0 = fmaxf(tm0, fmaxf(s[nf][0], s[nf][1]));
            tm1 = fmaxf(tm1, fmaxf(s[nf][2], s[nf][3]));
        }
        tm0 = fmaxf(tm0, __shfl_xor_sync(0xffffffffu, tm0, 1));
        tm0 = fmaxf(tm0, __shfl_xor_sync(0xffffffffu, tm0, 2));
        tm1 = fmaxf(tm1, __shfl_xor_sync(0xffffffffu, tm1, 1));
        tm1 = fmaxf(tm1, __shfl_xor_sync(0xffffffffu, tm1, 2));
        float mn0 = fmaxf(mr0, tm0), mn1 = fmaxf(mr1, tm1);
        float c0 = __expf(mr0 - mn0), c1 = __expf(mr1 - mn1);
        mr0 = mn0; mr1 = mn1;
#pragma unroll
        for (int nf = 0; nf < 16; nf++) {
            o[nf][0] *= c0; o[nf][1] *= c0; o[nf][2] *= c1; o[nf][3] *= c1;
        }

        // G(t) ready (only outstanding group is G(t) after K wait above retired K)
        if (t + 1 < NTILES) { CP_WAIT_1(); } else { CP_WAIT_ALL(); }
        __syncthreads();

        // ---- interleaved exp + PV (half-blocks) ----
        float rs0 = 0.0f, rs1 = 0.0f;
#pragma unroll
        for (int half = 0; half < 2; half++) {
            uint32_t ph[8][2];
#pragma unroll
            for (int j = 0; j < 8; j++) {
                int nf = half * 8 + j;
                float p0 = __expf(s[nf][0] - mn0);
                float p1 = __expf(s[nf][1] - mn0);
                float p2 = __expf(s[nf][2] - mn1);
                float p3 = __expf(s[nf][3] - mn1);
                rs0 += p0 + p1; rs1 += p2 + p3;
                ph[j][0] = packh2(__float2half_rn(p0), __float2half_rn(p1));
                ph[j][1] = packh2(__float2half_rn(p2), __float2half_rn(p3));
            }
#pragma unroll
            for (int k2 = 0; k2 < 4; k2++) {
                int kk = half * 4 + k2;
                uint32_t a0 = ph[2 * k2][0], a1 = ph[2 * k2][1];
                uint32_t a2 = ph[2 * k2 + 1][0], a3 = ph[2 * k2 + 1][1];
#pragma unroll
                for (int np = 0; np < 8; np++) {
                    uint32_t gh[4];
                    ldsm4(gh[0], gh[1], gh[2], gh[3], sw_addr(sb + A_GHI, np * 16 + frow, kk * 2 + fhalf));
                    mma16816(o[2 * np],     a0, a1, a2, a3, gh[0], gh[2]);
                    mma16816(o[2 * np + 1], a0, a1, a2, a3, gh[1], gh[3]);
                }
            }
        }
        rs0 += __shfl_xor_sync(0xffffffffu, rs0, 1);
        rs0 += __shfl_xor_sync(0xffffffffu, rs0, 2);
        rs1 += __shfl_xor_sync(0xffffffffu, rs1, 1);
        rs1 += __shfl_xor_sync(0xffffffffu, rs1, 2);
        lr0 = lr0 * c0 + rs0;
        lr1 = lr1 * c1 + rs1;

        // GHI free -> prefetch G(t+1) (covered by next tile's S)
        __syncthreads();
        if (t + 1 < NTILES) {
            const int m1 = (t + 1) * 128;
            load_tile128_a128(sb + A_GHI, d_g_hi + (size_t)b * CI * NN + m1, NN);
            CP_COMMIT();
        }
    }

    // epilogue: y = O / l, split hi/lo, store directly as [b][n][c] fp16
    const float inv0 = 1.0f / lr0, inv1 = 1.0f / lr1;
    const int q0 = n0 + w * 16 + (lane >> 2);
    __half* yh0 = d_y_hi + (size_t)(b * NN + q0) * CI;
    __half* yl0 = d_y_lo + (size_t)(b * NN + q0) * CI;
    __half* yh1 = d_y_hi + (size_t)(b * NN + q0 + 8) * CI;
    __half* yl1 = d_y_lo + (size_t)(b * NN + q0 + 8) * CI;
#pragma unroll
    for (int nf = 0; nf < 16; nf++) {
        int c = nf * 8 + (lane & 3) * 2;
        float v0 = o[nf][0] * inv0, v1 = o[nf][1] * inv0;
        float v2 = o[nf][2] * inv1, v3 = o[nf][3] * inv1;
        __half h0 = __float2half_rn(v0), h1 = __float2half_rn(v1);
        __half h2 = __float2half_rn(v2), h3 = __float2half_rn(v3);
        *(__half2*)(yh0 + c) = __halves2half2(h0, h1);
        *(__half2*)(yl0 + c) = __halves2half2(__float2half_rn(v0 - __half2float(h0)),
                                              __float2half_rn(v1 - __half2float(h1)));
        *(__half2*)(yh1 + c) = __halves2half2(h2, h3);
        *(__half2*)(yl1 + c) = __halves2half2(__float2half_rn(v2 - __half2float(h2)),
                                              __float2half_rn(v3 - __half2float(h3)));
    }
}

// ---------------- Kernel 4: tensor-core W GEMM + bias + residual + fused stats ----------------
__global__ __launch_bounds__(256, 1) void wgemm_tc_kernel(
    const float* __restrict__ x,
    const float* __restrict__ Ww, const float* __restrict__ Wb)
{
    extern __shared__ char smem[];
    const uint32_t sb = smem_u32(smem);
    const int t = threadIdx.x;
    const int lane = t & 31, w = t >> 5;
    const int b = blockIdx.z;
    const int o0 = blockIdx.y * 128;
    const int n0 = blockIdx.x * 128;

    const int frow = lane & 15, fhalf = lane >> 4;
    const int arow = w * 16 + frow;

    split_tile(sb + TG_A_HI, sb + TG_A_LO, Ww + (size_t)o0 * CI, CI);
    load_tile(sb + TG_B_HI, d_y_hi + (size_t)(b * NN + n0) * CI, CI);
    load_tile(sb + TG_B_LO, d_y_lo + (size_t)(b * NN + n0) * CI, CI);
    __syncthreads();

    float acc[16][4];
#pragma unroll
    for (int nf = 0; nf < 16; nf++)
#pragma unroll
        for (int j = 0; j < 4; j++) acc[nf][j] = 0.0f;

#pragma unroll 1
    for (int kk = 0; kk < 8; kk++) {
        uint32_t ah[4], al[4];
        ldsm4(ah[0], ah[1], ah[2], ah[3], sw_addr(sb + TG_A_HI, arow, kk * 2 + fhalf));
        ldsm4(al[0], al[1], al[2], al[3], sw_addr(sb + TG_A_LO, arow, kk * 2 + fhalf));
#pragma unroll
        for (int np = 0; np < 8; np++) {
            uint32_t bh[4], bl[4];
            ldsm4(bh[0], bh[1], bh[2], bh[3], sw_addr(sb + TG_B_HI, np * 16 + frow, kk * 2 + fhalf));
            ldsm4(bl[0], bl[1], bl[2], bl[3], sw_addr(sb + TG_B_LO, np * 16 + frow, kk * 2 + fhalf));
            mma16816(acc[2 * np],     ah[0], ah[1], ah[2], ah[3], bh[0], bh[2]);
            mma16816(acc[2 * np + 1], ah[0], ah[1], ah[2], ah[3], bh[1], bh[3]);
            mma16816(acc[2 * np],     ah[0], ah[1], ah[2], ah[3], bl[0], bl[2]);
            mma16816(acc[2 * np + 1], ah[0], ah[1], ah[2], ah[3], bl[1], bl[3]);
            mma16816(acc[2 * np],     al[0], al[1], al[2], al[3], bh[0], bh[2]);
            mma16816(acc[2 * np + 1], al[0], al[1], al[2], al[3], bh[1], bh[3]);
        }
    }

    const int rl = o0 + w * 16 + (lane >> 2);
    const float bias0 = Wb[rl], bias1 = Wb[rl + 8];
    const float* xr0 = x + (size_t)(b * COUT + rl) * NN + n0;
    const float* xr1 = x + (size_t)(b * COUT + rl + 8) * NN + n0;
    float* z0 = d_z + (size_t)rl * (BB * NN) + (size_t)b * NN + n0;
    float* z1 = d_z + (size_t)(rl + 8) * (BB * NN) + (size_t)b * NN + n0;
    float s0 = 0.f, q0 = 0.f, s1 = 0.f, q1 = 0.f;
#pragma unroll
    for (int nf = 0; nf < 16; nf++) {
        int n = nf * 8 + (lane & 3) * 2;
        float2 xa = *(const float2*)(xr0 + n);
        float2 xb = *(const float2*)(xr1 + n);
        float v00 = acc[nf][0] + bias0 + xa.x, v01 = acc[nf][1] + bias0 + xa.y;
        float v10 = acc[nf][2] + bias1 + xb.x, v11 = acc[nf][3] + bias1 + xb.y;
        *(float2*)(z0 + n) = make_float2(v00, v01);
        *(float2*)(z1 + n) = make_float2(v10, v11);
        s0 += v00 + v01; q0 += v00 * v00 + v01 * v01;
        s1 += v10 + v11; q1 += v10 * v10 + v11 * v11;
    }
    s0 += __shfl_xor_sync(0xffffffffu, s0, 1); s0 += __shfl_xor_sync(0xffffffffu, s0, 2);
    q0 += __shfl_xor_sync(0xffffffffu, q0, 1); q0 += __shfl_xor_sync(0xffffffffu, q0, 2);
    s1 += __shfl_xor_sync(0xffffffffu, s1, 1); s1 += __shfl_xor_sync(0xffffffffu, s1, 2);
    q1 += __shfl_xor_sync(0xffffffffu, q1, 1); q1 += __shfl_xor_sync(0xffffffffu, q1, 2);
    if ((lane & 3) == 0) {
        atomicAdd(&d_zsum[rl], s0);     atomicAdd(&d_zsumsq[rl], q0);
        atomicAdd(&d_zsum[rl + 8], s1); atomicAdd(&d_zsumsq[rl + 8], q1);
    }
}

// ---------------- final normalize (BN finalize fused per-thread) ----------------
__global__ __launch_bounds__(256) void finalize_kernel(
    const float* __restrict__ bn_gamma, const float* __restrict__ bn_beta,
    float* __restrict__ out)
{
    int idx = blockIdx.x * 256 + threadIdx.x;
    int o = idx >> 14;
    int rem = idx & 16383;
    int b = rem >> 12;
    int n = rem & 4095;
    float mean = d_zsum[o] * (1.0f / (BB * NN));
    float var = d_zsumsq[o] * (1.0f / (BB * NN)) - mean * mean;
    float sc = bn_gamma[o] * rsqrtf(var + BN_EPS);
    float sh = bn_beta[o] - mean * sc;
    out[(b * COUT + o) * NN + n] = d_z[idx] * sc + sh;
}

// ---------------- host launcher ----------------
extern "C" void kernel_launch(void* const* d_in, const int* in_sizes, int n_in,
                              void* d_out, int out_size)
{
    const float* x        = (const float*)d_in[0];
    const float* g_w      = (const float*)d_in[1];
    const float* g_b      = (const float*)d_in[2];
    const float* g_gamma  = (const float*)d_in[3];
    const float* g_beta   = (const float*)d_in[4];
    const float* th_w     = (const float*)d_in[5];
    const float* th_b     = (const float*)d_in[6];
    const float* th_gamma = (const float*)d_in[7];
    const float* th_beta  = (const float*)d_in[8];
    const float* ph_w     = (const float*)d_in[9];
    const float* ph_b     = (const float*)d_in[10];
    const float* ph_gamma = (const float*)d_in[11];
    const float* ph_beta  = (const float*)d_in[12];
    const float* W_w      = (const float*)d_in[13];
    const float* W_b      = (const float*)d_in[14];
    const float* bn_gamma = (const float*)d_in[15];
    const float* bn_beta  = (const float*)d_in[16];
    float* out = (float*)d_out;

    cudaFuncSetAttribute(proj_tc_kernel, cudaFuncAttributeMaxDynamicSharedMemorySize, TG_SMEM_BYTES);
    cudaFuncSetAttribute(wgemm_tc_kernel, cudaFuncAttributeMaxDynamicSharedMemorySize, TG_SMEM_BYTES);
    cudaFuncSetAttribute(attn_mma_kernel, cudaFuncAttributeMaxDynamicSharedMemorySize, ATTN_SMEM_BYTES);

    prep_xt_kernel<<<dim3(NN / 32, CIN / 32, BB), 256>>>(x);
    proj_tc_kernel<<<dim3(NN / 128, CP / 128, BB), 256, TG_SMEM_BYTES>>>(
        g_w, g_b, th_w, th_b, ph_w, ph_b);
    prep_qkg_kernel<<<dim3(NN / 32, CI / 32, BB * 3), 256>>>(
        g_gamma, g_beta, th_gamma, th_beta, ph_gamma, ph_beta);
    attn_mma_kernel<<<dim3(NN / 64, BB), 128, ATTN_SMEM_BYTES>>>();
    wgemm_tc_kernel<<<dim3(NN / 128, COUT / 128, BB), 256, TG_SMEM_BYTES>>>(x, W_w, W_b);
    finalize_kernel<<<(COUT * BB * NN) / 256, 256>>>(bn_gamma, bn_beta, out);
}

// round 15
// speedup vs baseline: 1.1106x; 1.0005x over previous
#include <cuda_runtime.h>
#include <cuda_fp16.h>
#include <math.h>
#include <stdint.h>

// Problem constants
#define BB 4
#define CIN 256
#define CI 128
#define NN 4096          // H*W = 64*64
#define CP 384           // 3*CI projection channels
#define COUT 256
#define BN_EPS 1e-5f
#define NTILES 32        // NN / 128 key tiles

// Scratch (static device globals; allocation APIs are forbidden)
__device__ float d_proj[CP * BB * NN];     // [m][b][n]
__device__ float d_psum[CP];
__device__ float d_psumsq[CP];
__device__ float d_z[COUT * BB * NN];      // [o][b][n]
__device__ float d_zsum[COUT];
__device__ float d_zsumsq[COUT];

// fp16 hi/lo split operands
__device__ __half d_xt_hi[BB * NN * CIN];  // x^T      [b][n][c]
__device__ __half d_xt_lo[BB * NN * CIN];
__device__ __half d_th_hi[BB * NN * CI];   // theta^T  [b][n][c]
__device__ __half d_th_lo[BB * NN * CI];
__device__ __half d_ph_hi[BB * NN * CI];   // phi^T    [b][n][c]
__device__ __half d_ph_lo[BB * NN * CI];
__device__ __half d_g_hi[BB * CI * NN];    // g        [b][c][n]
__device__ __half d_y_hi[BB * NN * CI];    // y^T      [b][n][c]
__device__ __half d_y_lo[BB * NN * CI];

// ======================= helpers =======================
__device__ __forceinline__ uint32_t smem_u32(const void* p) {
    uint32_t a;
    asm("{ .reg .u64 t; cvta.to.shared.u64 t, %1; cvt.u32.u64 %0, t; }" : "=r"(a) : "l"(p));
    return a;
}

__device__ __forceinline__ void ldsm4(uint32_t& r0, uint32_t& r1, uint32_t& r2, uint32_t& r3,
                                      uint32_t addr) {
    asm volatile("ldmatrix.sync.aligned.m8n8.x4.shared.b16 {%0,%1,%2,%3}, [%4];"
                 : "=r"(r0), "=r"(r1), "=r"(r2), "=r"(r3) : "r"(addr));
}

__device__ __forceinline__ void mma16816(float* d, uint32_t a0, uint32_t a1, uint32_t a2, uint32_t a3,
                                         uint32_t b0, uint32_t b1) {
    asm volatile(
        "mma.sync.aligned.m16n8k16.row.col.f32.f16.f16.f32 "
        "{%0,%1,%2,%3}, {%4,%5,%6,%7}, {%8,%9}, {%0,%1,%2,%3};"
        : "+f"(d[0]), "+f"(d[1]), "+f"(d[2]), "+f"(d[3])
        : "r"(a0), "r"(a1), "r"(a2), "r"(a3), "r"(b0), "r"(b1));
}

__device__ __forceinline__ uint32_t sw_addr(uint32_t base, int row, int chunk) {
    return base + (uint32_t)row * 256u + (uint32_t)((chunk ^ (row & 7)) << 4);
}

__device__ __forceinline__ uint32_t packh2(__half a, __half b) {
    __half2 h = __halves2half2(a, b);
    return *(uint32_t*)&h;
}

__device__ __forceinline__ void cpasync16(uint32_t dst, const void* src) {
    asm volatile("cp.async.cg.shared.global [%0], [%1], 16;" :: "r"(dst), "l"(src));
}
#define CP_COMMIT()   asm volatile("cp.async.commit_group;" ::: "memory")
#define CP_WAIT_ALL() asm volatile("cp.async.wait_group 0;" ::: "memory")
#define CP_WAIT_1()   asm volatile("cp.async.wait_group 1;" ::: "memory")

// 256-thread cooperative tile loaders (GEMM kernels)
__device__ __forceinline__ void load_tile_a256(uint32_t dst, const __half* __restrict__ src,
                                               int row_stride) {
    const int t = threadIdx.x;
#pragma unroll
    for (int i = 0; i < 8; i++) {
        int cid = i * 256 + t;
        int row = cid >> 4, c = cid & 15;
        cpasync16(sw_addr(dst, row, c), src + (size_t)row * row_stride + c * 8);
    }
}

// 128-thread async loaders (attention)
__device__ __forceinline__ void load_tile128_a128(uint32_t dst, const __half* __restrict__ src,
                                                  int row_stride) {
    const int t = threadIdx.x;
#pragma unroll
    for (int i = 0; i < 16; i++) {
        int cid = i * 128 + t;
        int row = cid >> 4, c = cid & 15;
        cpasync16(sw_addr(dst, row, c), src + (size_t)row * row_stride + c * 8);
    }
}
__device__ __forceinline__ void load_tile64_a128(uint32_t dst, const __half* __restrict__ src,
                                                 int row_stride) {
    const int t = threadIdx.x;
#pragma unroll
    for (int i = 0; i < 8; i++) {
        int cid = i * 128 + t;
        int row = cid >> 4, c = cid & 15;
        cpasync16(sw_addr(dst, row, c), src + (size_t)row * row_stride + c * 8);
    }
}

__device__ __forceinline__ void split_tile(uint32_t dhi, uint32_t dlo,
                                           const float* __restrict__ src, int row_stride) {
    const int t = threadIdx.x;
#pragma unroll
    for (int i = 0; i < 8; i++) {
        int cid = i * 256 + t;
        int row = cid >> 4, c = cid & 15;
        const float* p = src + (size_t)row * row_stride + c * 8;
        float4 v0 = *(const float4*)p;
        float4 v1 = *(const float4*)(p + 4);
        float e[8] = {v0.x, v0.y, v0.z, v0.w, v1.x, v1.y, v1.z, v1.w};
        __half h[8], l[8];
#pragma unroll
        for (int j = 0; j < 8; j++) {
            h[j] = __float2half_rn(e[j]);
            l[j] = __float2half_rn(e[j] - __half2float(h[j]));
        }
        asm volatile("st.shared.v4.b32 [%0], {%1, %2, %3, %4};"
                     :: "r"(sw_addr(dhi, row, c)), "r"(packh2(h[0], h[1])), "r"(packh2(h[2], h[3])),
                        "r"(packh2(h[4], h[5])), "r"(packh2(h[6], h[7])));
        asm volatile("st.shared.v4.b32 [%0], {%1, %2, %3, %4};"
                     :: "r"(sw_addr(dlo, row, c)), "r"(packh2(l[0], l[1])), "r"(packh2(l[2], l[3])),
                        "r"(packh2(l[4], l[5])), "r"(packh2(l[6], l[7])));
    }
}

// ---------------- Kernel 0: transpose+split x (+ zero stats in block 0) ----------------
__global__ __launch_bounds__(256) void prep_xt_kernel(const float* __restrict__ x)
{
    __shared__ float tile[32][33];
    const int t = threadIdx.x;
    if (blockIdx.x == 0 && blockIdx.y == 0 && blockIdx.z == 0) {
        for (int i = t; i < CP; i += 256) { d_psum[i] = 0.0f; d_psumsq[i] = 0.0f; }
        if (t < COUT) { d_zsum[t] = 0.0f; d_zsumsq[t] = 0.0f; }
    }
    const int tx = t & 31, ty = t >> 5;
    const int b = blockIdx.z;
    const int c0 = blockIdx.y * 32;
    const int n0 = blockIdx.x * 32;
#pragma unroll
    for (int i = 0; i < 4; i++) {
        int c = c0 + ty + i * 8;
        tile[ty + i * 8][tx] = x[(size_t)(b * CIN + c) * NN + n0 + tx];
    }
    __syncthreads();
#pragma unroll
    for (int i = 0; i < 4; i++) {
        int n = n0 + ty + i * 8;
        float v = tile[tx][ty + i * 8];
        __half h = __float2half_rn(v);
        __half l = __float2half_rn(v - __half2float(h));
        size_t idx = (size_t)(b * NN + n) * CIN + c0 + tx;
        d_xt_hi[idx] = h;
        d_xt_lo[idx] = l;
    }
}

// ---------------- Kernel 1: tensor-core projection GEMM, async B, + fused stats ----------------
#define P_A_HI 0
#define P_A_LO 32768
#define P_B0_HI 65536
#define P_B0_LO 98304
#define P_B1_HI 131072
#define P_B1_LO 163840
#define P_SMEM_BYTES 196608

__global__ __launch_bounds__(256, 1) void proj_tc_kernel(
    const float* __restrict__ gw, const float* __restrict__ gb,
    const float* __restrict__ thw, const float* __restrict__ thb,
    const float* __restrict__ phw, const float* __restrict__ phb)
{
    extern __shared__ char smem[];
    const uint32_t sb = smem_u32(smem);
    const int t = threadIdx.x;
    const int lane = t & 31, w = t >> 5;
    const int b = blockIdx.z;
    const int m0 = blockIdx.y * 128;
    const int n0 = blockIdx.x * 128;

    const float* wsrc;
    const float* bsrc;
    if (m0 == 0)        { wsrc = gw;  bsrc = gb;  }
    else if (m0 == 128) { wsrc = thw; bsrc = thb; }
    else                { wsrc = phw; bsrc = phb; }

    const int frow = lane & 15, fhalf = lane >> 4;
    const int arow = w * 16 + frow;

    // prologue: async-prefetch both B chunks (x^T hi/lo, fp16 in global)
    const __half* bhi = d_xt_hi + (size_t)(b * NN + n0) * CIN;
    const __half* blo = d_xt_lo + (size_t)(b * NN + n0) * CIN;
    load_tile_a256(sb + P_B0_HI, bhi, CIN);
    load_tile_a256(sb + P_B0_LO, blo, CIN);
    CP_COMMIT();
    load_tile_a256(sb + P_B1_HI, bhi + 128, CIN);
    load_tile_a256(sb + P_B1_LO, blo + 128, CIN);
    CP_COMMIT();

    float acc[16][4];
#pragma unroll
    for (int nf = 0; nf < 16; nf++)
#pragma unroll
        for (int j = 0; j < 4; j++) acc[nf][j] = 0.0f;

#pragma unroll 1
    for (int ch = 0; ch < 2; ch++) {
        if (ch == 1) __syncthreads();              // A-smem readers from chunk 0 done
        split_tile(sb + P_A_HI, sb + P_A_LO, wsrc + ch * 128, CIN);
        if (ch == 0) { CP_WAIT_1(); } else { CP_WAIT_ALL(); }
        __syncthreads();
        const uint32_t BHI = sb + (ch ? P_B1_HI : P_B0_HI);
        const uint32_t BLO = sb + (ch ? P_B1_LO : P_B0_LO);

#pragma unroll 1
        for (int kk = 0; kk < 8; kk++) {
            uint32_t ah[4], al[4];
            ldsm4(ah[0], ah[1], ah[2], ah[3], sw_addr(sb + P_A_HI, arow, kk * 2 + fhalf));
            ldsm4(al[0], al[1], al[2], al[3], sw_addr(sb + P_A_LO, arow, kk * 2 + fhalf));
#pragma unroll
            for (int np = 0; np < 8; np++) {
                uint32_t bh[4], bl[4];
                ldsm4(bh[0], bh[1], bh[2], bh[3], sw_addr(BHI, np * 16 + frow, kk * 2 + fhalf));
                ldsm4(bl[0], bl[1], bl[2], bl[3], sw_addr(BLO, np * 16 + frow, kk * 2 + fhalf));
                mma16816(acc[2 * np],     ah[0], ah[1], ah[2], ah[3], bh[0], bh[2]);
                mma16816(acc[2 * np + 1], ah[0], ah[1], ah[2], ah[3], bh[1], bh[3]);
                mma16816(acc[2 * np],     ah[0], ah[1], ah[2], ah[3], bl[0], bl[2]);
                mma16816(acc[2 * np + 1], ah[0], ah[1], ah[2], ah[3], bl[1], bl[3]);
                mma16816(acc[2 * np],     al[0], al[1], al[2], al[3], bh[0], bh[2]);
                mma16816(acc[2 * np + 1], al[0], al[1], al[2], al[3], bh[1], bh[3]);
            }
        }
    }

    const int rl = w * 16 + (lane >> 2);
    const float bias0 = bsrc[rl];
    const float bias1 = bsrc[rl + 8];
    float* out0 = d_proj + (size_t)(m0 + rl) * (BB * NN) + (size_t)b * NN + n0;
    float* out1 = d_proj + (size_t)(m0 + rl + 8) * (BB * NN) + (size_t)b * NN + n0;
    float s0 = 0.f, q0 = 0.f, s1 = 0.f, q1 = 0.f;
#pragma unroll
    for (int nf = 0; nf < 16; nf++) {
        int n = nf * 8 + (lane & 3) * 2;
        float v00 = acc[nf][0] + bias0, v01 = acc[nf][1] + bias0;
        float v10 = acc[nf][2] + bias1, v11 = acc[nf][3] + bias1;
        *(float2*)(out0 + n) = make_float2(v00, v01);
        *(float2*)(out1 + n) = make_float2(v10, v11);
        s0 += v00 + v01; q0 += v00 * v00 + v01 * v01;
        s1 += v10 + v11; q1 += v10 * v10 + v11 * v11;
    }
    s0 += __shfl_xor_sync(0xffffffffu, s0, 1); s0 += __shfl_xor_sync(0xffffffffu, s0, 2);
    q0 += __shfl_xor_sync(0xffffffffu, q0, 1); q0 += __shfl_xor_sync(0xffffffffu, q0, 2);
    s1 += __shfl_xor_sync(0xffffffffu, s1, 1); s1 += __shfl_xor_sync(0xffffffffu, s1, 2);
    q1 += __shfl_xor_sync(0xffffffffu, q1, 1); q1 += __shfl_xor_sync(0xffffffffu, q1, 2);
    if ((lane & 3) == 0) {
        atomicAdd(&d_psum[m0 + rl], s0);     atomicAdd(&d_psumsq[m0 + rl], q0);
        atomicAdd(&d_psum[m0 + rl + 8], s1); atomicAdd(&d_psumsq[m0 + rl + 8], q1);
    }
}

// ---------------- prep theta/phi/g (BN applied from raw sums) ----------------
__global__ __launch_bounds__(256) void prep_qkg_kernel(
    const float* __restrict__ g_gamma, const float* __restrict__ g_beta,
    const float* __restrict__ th_gamma, const float* __restrict__ th_beta,
    const float* __restrict__ ph_gamma, const float* __restrict__ ph_beta)
{
    __shared__ float tile[32][33];
    __shared__ float sscale[32], sshift[32];
    const int t = threadIdx.x;
    const int tx = t & 31, ty = t >> 5;
    const int sel = blockIdx.z >> 2;      // 0 theta, 1 phi, 2 g
    const int b = blockIdx.z & 3;
    const int c0 = blockIdx.y * 32;
    const int n0 = blockIdx.x * 32;
    const int chbase = (sel == 2) ? 0 : (128 + sel * 128);
    if (t < 32) {
        int ch = chbase + c0 + t;
        float mean = d_psum[ch] * (1.0f / (BB * NN));
        float var = d_psumsq[ch] * (1.0f / (BB * NN)) - mean * mean;
        float gamma, beta;
        if (sel == 0)      { gamma = th_gamma[c0 + t]; beta = th_beta[c0 + t]; }
        else if (sel == 1) { gamma = ph_gamma[c0 + t]; beta = ph_beta[c0 + t]; }
        else               { gamma = g_gamma[c0 + t];  beta = g_beta[c0 + t]; }
        float sc = gamma * rsqrtf(var + BN_EPS);
        sscale[t] = sc;
        sshift[t] = beta - mean * sc;
    }
    __syncthreads();
    if (sel == 2) {
#pragma unroll
        for (int i = 0; i < 4; i++) {
            int cc = ty + i * 8;
            int c = c0 + cc;
            float v = d_proj[(size_t)c * (BB * NN) + (size_t)b * NN + n0 + tx];
            float r = v * sscale[cc] + sshift[cc];
            d_g_hi[(size_t)(b * CI + c) * NN + n0 + tx] = __float2half_rn(r);
        }
        return;
    }
#pragma unroll
    for (int i = 0; i < 4; i++) {
        int cc = ty + i * 8;
        float v = d_proj[(size_t)(chbase + c0 + cc) * (BB * NN) + (size_t)b * NN + n0 + tx];
        tile[cc][tx] = v * sscale[cc] + sshift[cc];
    }
    __syncthreads();
    __half* hi = sel ? d_ph_hi : d_th_hi;
    __half* lo = sel ? d_ph_lo : d_th_lo;
#pragma unroll
    for (int i = 0; i < 4; i++) {
        int n = n0 + ty + i * 8;
        float v = tile[tx][ty + i * 8];
        __half h = __float2half_rn(v);
        __half l = __float2half_rn(v - __half2float(h));
        size_t idx = (size_t)(b * NN + n) * CI + c0 + tx;
        hi[idx] = h;
        lo[idx] = l;
    }
}

// ---------------- Kernel 3: 2-CTA/SM desynced flash attention (R11 config, verbatim) ----------------
#define A_QLO 0          // 64 x 256B = 16KB
#define A_KHI 16384
#define A_KLO 49152
#define A_GHI 81920
#define ATTN_SMEM_BYTES 114688

__global__ __launch_bounds__(128, 2) void attn_mma_kernel()
{
    extern __shared__ char smem[];
    const uint32_t sb = smem_u32(smem);
    const int tid = threadIdx.x;
    const int lane = tid & 31;
    const int w = tid >> 5;          // 0..3
    const int b = blockIdx.y;
    const int n0 = blockIdx.x * 64;

    const int frow = lane & 15;
    const int fhalf = lane >> 4;
    const int arow = w * 16 + frow;

    // ---- stage Qhi via GHI buffer; Qlo into QLO ----
    load_tile64_a128(sb + A_GHI, d_th_hi + (size_t)(b * NN + n0) * CI, CI);
    load_tile64_a128(sb + A_QLO, d_th_lo + (size_t)(b * NN + n0) * CI, CI);
    CP_COMMIT(); CP_WAIT_ALL(); __syncthreads();
    uint32_t qh[8][4];
#pragma unroll
    for (int kk = 0; kk < 8; kk++)
        ldsm4(qh[kk][0], qh[kk][1], qh[kk][2], qh[kk][3], sw_addr(sb + A_GHI, arow, kk * 2 + fhalf));
    __syncthreads();

    // ---- prologue prefetch: K(0) group, then G(0) group ----
    load_tile128_a128(sb + A_KHI, d_ph_hi + (size_t)(b * NN) * CI, CI);
    load_tile128_a128(sb + A_KLO, d_ph_lo + (size_t)(b * NN) * CI, CI);
    CP_COMMIT();
    load_tile128_a128(sb + A_GHI, d_g_hi + (size_t)b * CI * NN, NN);
    CP_COMMIT();

    float o[16][4];
#pragma unroll
    for (int nf = 0; nf < 16; nf++)
#pragma unroll
        for (int j = 0; j < 4; j++) o[nf][j] = 0.0f;
    float mr0 = -INFINITY, mr1 = -INFINITY, lr0 = 0.0f, lr1 = 0.0f;

#pragma unroll 1
    for (int t = 0; t < NTILES; t++) {
        // K(t) ready (G(t) may still be in flight)
        CP_WAIT_1();
        __syncthreads();

        // ---- S = Qh*Kh^T + Qh*Kl^T + Ql*Kh^T ----
        float s[16][4];
#pragma unroll
        for (int nf = 0; nf < 16; nf++)
#pragma unroll
            for (int j = 0; j < 4; j++) s[nf][j] = 0.0f;

#pragma unroll 1
        for (int kk = 0; kk < 8; kk++) {
            uint32_t ql[4];
            ldsm4(ql[0], ql[1], ql[2], ql[3], sw_addr(sb + A_QLO, arow, kk * 2 + fhalf));
#pragma unroll
            for (int np = 0; np < 8; np++) {
                uint32_t kh[4], kl[4];
                ldsm4(kh[0], kh[1], kh[2], kh[3], sw_addr(sb + A_KHI, np * 16 + frow, kk * 2 + fhalf));
                ldsm4(kl[0], kl[1], kl[2], kl[3], sw_addr(sb + A_KLO, np * 16 + frow, kk * 2 + fhalf));
                mma16816(s[2 * np],     qh[kk][0], qh[kk][1], qh[kk][2], qh[kk][3], kh[0], kh[2]);
                mma16816(s[2 * np + 1], qh[kk][0], qh[kk][1], qh[kk][2], qh[kk][3], kh[1], kh[3]);
                mma16816(s[2 * np],     qh[kk][0], qh[kk][1], qh[kk][2], qh[kk][3], kl[0], kl[2]);
                mma16816(s[2 * np + 1], qh[kk][0], qh[kk][1], qh[kk][2], qh[kk][3], kl[1], kl[3]);
                mma16816(s[2 * np],     ql[0], ql[1], ql[2], ql[3], kh[0], kh[2]);
                mma16816(s[2 * np + 1], ql[0], ql[1], ql[2], ql[3], kh[1], kh[3]);
            }
        }

        // K buffers free -> prefetch K(t+1) (covered by softmax+PV below)
        __syncthreads();
        if (t + 1 < NTILES) {
            const int m1 = (t + 1) * 128;
            load_tile128_a128(sb + A_KHI, d_ph_hi + (size_t)(b * NN + m1) * CI, CI);
            load_tile128_a128(sb + A_KLO, d_ph_lo + (size_t)(b * NN + m1) * CI, CI);
            CP_COMMIT();
        }

        // ---- softmax max/rescale (register-only; overlaps G(t) arrival) ----
        float tm0 = -INFINITY, tm1 = -INFINITY;
#pragma unroll
        for (int nf = 0; nf < 16; nf++) {
            tm0 = fmaxf(tm0, fmaxf(s[nf][0], s[nf][1]));
            tm1 = fmaxf(tm1, fmaxf(s[nf][2], s[nf][3]));
        }
        tm0 = fmaxf(tm0, __shfl_xor_sync(0xffffffffu, tm0, 1));
        tm0 = fmaxf(tm0, __shfl_xor_sync(0xffffffffu, tm0, 2));
        tm1 = fmaxf(tm1, __shfl_xor_sync(0xffffffffu, tm1, 1));
        tm1 = fmaxf(tm1, __shfl_xor_sync(0xffffffffu, tm1, 2));
        float mn0 = fmaxf(mr0, tm0), mn1 = fmaxf(mr1, tm1);
        float c0 = __expf(mr0 - mn0), c1 = __expf(mr1 - mn1);
        mr0 = mn0; mr1 = mn1;
#pragma unroll
        for (int nf = 0; nf < 16; nf++) {
            o[nf][0] *= c0; o[nf][1] *= c0; o[nf][2] *= c1; o[nf][3] *= c1;
        }

        // G(t) ready (G(t) committed before K(t+1): retire order guarantees G landed)
        if (t + 1 < NTILES) { CP_WAIT_1(); } else { CP_WAIT_ALL(); }
        __syncthreads();

        // ---- interleaved exp + PV (half-blocks) ----
        float rs0 = 0.0f, rs1 = 0.0f;
#pragma unroll
        for (int half = 0; half < 2; half++) {
            uint32_t ph[8][2];
#pragma unroll
            for (int j = 0; j < 8; j++) {
                int nf = half * 8 + j;
                float p0 = __expf(s[nf][0] - mn0);
                float p1 = __expf(s[nf][1] - mn0);
                float p2 = __expf(s[nf][2] - mn1);
                float p3 = __expf(s[nf][3] - mn1);
                rs0 += p0 + p1; rs1 += p2 + p3;
                ph[j][0] = packh2(__float2half_rn(p0), __float2half_rn(p1));
                ph[j][1] = packh2(__float2half_rn(p2), __float2half_rn(p3));
            }
#pragma unroll
            for (int k2 = 0; k2 < 4; k2++) {
                int kk = half * 4 + k2;
                uint32_t a0 = ph[2 * k2][0], a1 = ph[2 * k2][1];
                uint32_t a2 = ph[2 * k2 + 1][0], a3 = ph[2 * k2 + 1][1];
#pragma unroll
                for (int np = 0; np < 8; np++) {
                    uint32_t gh[4];
                    ldsm4(gh[0], gh[1], gh[2], gh[3], sw_addr(sb + A_GHI, np * 16 + frow, kk * 2 + fhalf));
                    mma16816(o[2 * np],     a0, a1, a2, a3, gh[0], gh[2]);
                    mma16816(o[2 * np + 1], a0, a1, a2, a3, gh[1], gh[3]);
                }
            }
        }
        rs0 += __shfl_xor_sync(0xffffffffu, rs0, 1);
        rs0 += __shfl_xor_sync(0xffffffffu, rs0, 2);
        rs1 += __shfl_xor_sync(0xffffffffu, rs1, 1);
        rs1 += __shfl_xor_sync(0xffffffffu, rs1, 2);
        lr0 = lr0 * c0 + rs0;
        lr1 = lr1 * c1 + rs1;

        // GHI free -> prefetch G(t+1) (covered by next tile's S)
        __syncthreads();
        if (t + 1 < NTILES) {
            const int m1 = (t + 1) * 128;
            load_tile128_a128(sb + A_GHI, d_g_hi + (size_t)b * CI * NN + m1, NN);
            CP_COMMIT();
        }
    }

    // epilogue: y = O / l, split hi/lo, store directly as [b][n][c] fp16
    const float inv0 = 1.0f / lr0, inv1 = 1.0f / lr1;
    const int q0 = n0 + w * 16 + (lane >> 2);
    __half* yh0 = d_y_hi + (size_t)(b * NN + q0) * CI;
    __half* yl0 = d_y_lo + (size_t)(b * NN + q0) * CI;
    __half* yh1 = d_y_hi + (size_t)(b * NN + q0 + 8) * CI;
    __half* yl1 = d_y_lo + (size_t)(b * NN + q0 + 8) * CI;
#pragma unroll
    for (int nf = 0; nf < 16; nf++) {
        int c = nf * 8 + (lane & 3) * 2;
        float v0 = o[nf][0] * inv0, v1 = o[nf][1] * inv0;
        float v2 = o[nf][2] * inv1, v3 = o[nf][3] * inv1;
        __half h0 = __float2half_rn(v0), h1 = __float2half_rn(v1);
        __half h2 = __float2half_rn(v2), h3 = __float2half_rn(v3);
        *(__half2*)(yh0 + c) = __halves2half2(h0, h1);
        *(__half2*)(yl0 + c) = __halves2half2(__float2half_rn(v0 - __half2float(h0)),
                                              __float2half_rn(v1 - __half2float(h1)));
        *(__half2*)(yh1 + c) = __halves2half2(h2, h3);
        *(__half2*)(yl1 + c) = __halves2half2(__float2half_rn(v2 - __half2float(h2)),
                                              __float2half_rn(v3 - __half2float(h3)));
    }
}

// ---------------- Kernel 4: W GEMM, async B, + bias + residual + fused stats ----------------
#define WG_A_HI 0
#define WG_A_LO 32768
#define WG_B_HI 65536
#define WG_B_LO 98304
#define WG_SMEM_BYTES 131072

__global__ __launch_bounds__(256, 1) void wgemm_tc_kernel(
    const float* __restrict__ x,
    const float* __restrict__ Ww, const float* __restrict__ Wb)
{
    extern __shared__ char smem[];
    const uint32_t sb = smem_u32(smem);
    const int t = threadIdx.x;
    const int lane = t & 31, w = t >> 5;
    const int b = blockIdx.z;
    const int o0 = blockIdx.y * 128;
    const int n0 = blockIdx.x * 128;

    const int frow = lane & 15, fhalf = lane >> 4;
    const int arow = w * 16 + frow;

    // async-prefetch B (y hi/lo), overlap with weight split
    load_tile_a256(sb + WG_B_HI, d_y_hi + (size_t)(b * NN + n0) * CI, CI);
    load_tile_a256(sb + WG_B_LO, d_y_lo + (size_t)(b * NN + n0) * CI, CI);
    CP_COMMIT();
    split_tile(sb + WG_A_HI, sb + WG_A_LO, Ww + (size_t)o0 * CI, CI);
    CP_WAIT_ALL();
    __syncthreads();

    float acc[16][4];
#pragma unroll
    for (int nf = 0; nf < 16; nf++)
#pragma unroll
        for (int j = 0; j < 4; j++) acc[nf][j] = 0.0f;

#pragma unroll 1
    for (int kk = 0; kk < 8; kk++) {
        uint32_t ah[4], al[4];
        ldsm4(ah[0], ah[1], ah[2], ah[3], sw_addr(sb + WG_A_HI, arow, kk * 2 + fhalf));
        ldsm4(al[0], al[1], al[2], al[3], sw_addr(sb + WG_A_LO, arow, kk * 2 + fhalf));
#pragma unroll
        for (int np = 0; np < 8; np++) {
            uint32_t bh[4], bl[4];
            ldsm4(bh[0], bh[1], bh[2], bh[3], sw_addr(sb + WG_B_HI, np * 16 + frow, kk * 2 + fhalf));
            ldsm4(bl[0], bl[1], bl[2], bl[3], sw_addr(sb + WG_B_LO, np * 16 + frow, kk * 2 + fhalf));
            mma16816(acc[2 * np],     ah[0], ah[1], ah[2], ah[3], bh[0], bh[2]);
            mma16816(acc[2 * np + 1], ah[0], ah[1], ah[2], ah[3], bh[1], bh[3]);
            mma16816(acc[2 * np],     ah[0], ah[1], ah[2], ah[3], bl[0], bl[2]);
            mma16816(acc[2 * np + 1], ah[0], ah[1], ah[2], ah[3], bl[1], bl[3]);
            mma16816(acc[2 * np],     al[0], al[1], al[2], al[3], bh[0], bh[2]);
            mma16816(acc[2 * np + 1], al[0], al[1], al[2], al[3], bh[1], bh[3]);
        }
    }

    const int rl = o0 + w * 16 + (lane >> 2);
    const float bias0 = Wb[rl], bias1 = Wb[rl + 8];
    const float* xr0 = x + (size_t)(b * COUT + rl) * NN + n0;
    const float* xr1 = x + (size_t)(b * COUT + rl + 8) * NN + n0;
    float* z0 = d_z + (size_t)rl * (BB * NN) + (size_t)b * NN + n0;
    float* z1 = d_z + (size_t)(rl + 8) * (BB * NN) + (size_t)b * NN + n0;
    float s0 = 0.f, q0 = 0.f, s1 = 0.f, q1 = 0.f;
#pragma unroll
    for (int nf = 0; nf < 16; nf++) {
        int n = nf * 8 + (lane & 3) * 2;
        float2 xa = *(const float2*)(xr0 + n);
        float2 xb = *(const float2*)(xr1 + n);
        float v00 = acc[nf][0] + bias0 + xa.x, v01 = acc[nf][1] + bias0 + xa.y;
        float v10 = acc[nf][2] + bias1 + xb.x, v11 = acc[nf][3] + bias1 + xb.y;
        *(float2*)(z0 + n) = make_float2(v00, v01);
        *(float2*)(z1 + n) = make_float2(v10, v11);
        s0 += v00 + v01; q0 += v00 * v00 + v01 * v01;
        s1 += v10 + v11; q1 += v10 * v10 + v11 * v11;
    }
    s0 += __shfl_xor_sync(0xffffffffu, s0, 1); s0 += __shfl_xor_sync(0xffffffffu, s0, 2);
    q0 += __shfl_xor_sync(0xffffffffu, q0, 1); q0 += __shfl_xor_sync(0xffffffffu, q0, 2);
    s1 += __shfl_xor_sync(0xffffffffu, s1, 1); s1 += __shfl_xor_sync(0xffffffffu, s1, 2);
    q1 += __shfl_xor_sync(0xffffffffu, q1, 1); q1 += __shfl_xor_sync(0xffffffffu, q1, 2);
    if ((lane & 3) == 0) {
        atomicAdd(&d_zsum[rl], s0);     atomicAdd(&d_zsumsq[rl], q0);
        atomicAdd(&d_zsum[rl + 8], s1); atomicAdd(&d_zsumsq[rl + 8], q1);
    }
}

// ---------------- final normalize (BN finalize fused per-thread) ----------------
__global__ __launch_bounds__(256) void finalize_kernel(
    const float* __restrict__ bn_gamma, const float* __restrict__ bn_beta,
    float* __restrict__ out)
{
    int idx = blockIdx.x * 256 + threadIdx.x;
    int o = idx >> 14;
    int rem = idx & 16383;
    int b = rem >> 12;
    int n = rem & 4095;
    float mean = d_zsum[o] * (1.0f / (BB * NN));
    float var = d_zsumsq[o] * (1.0f / (BB * NN)) - mean * mean;
    float sc = bn_gamma[o] * rsqrtf(var + BN_EPS);
    float sh = bn_beta[o] - mean * sc;
    out[(b * COUT + o) * NN + n] = d_z[idx] * sc + sh;
}

// ---------------- host launcher ----------------
extern "C" void kernel_launch(void* const* d_in, const int* in_sizes, int n_in,
                              void* d_out, int out_size)
{
    const float* x        = (const float*)d_in[0];
    const float* g_w      = (const float*)d_in[1];
    const float* g_b      = (const float*)d_in[2];
    const float* g_gamma  = (const float*)d_in[3];
    const float* g_beta   = (const float*)d_in[4];
    const float* th_w     = (const float*)d_in[5];
    const float* th_b     = (const float*)d_in[6];
    const float* th_gamma = (const float*)d_in[7];
    const float* th_beta  = (const float*)d_in[8];
    const float* ph_w     = (const float*)d_in[9];
    const float* ph_b     = (const float*)d_in[10];
    const float* ph_gamma = (const float*)d_in[11];
    const float* ph_beta  = (const float*)d_in[12];
    const float* W_w      = (const float*)d_in[13];
    const float* W_b      = (const float*)d_in[14];
    const float* bn_gamma = (const float*)d_in[15];
    const float* bn_beta  = (const float*)d_in[16];
    float* out = (float*)d_out;

    cudaFuncSetAttribute(proj_tc_kernel, cudaFuncAttributeMaxDynamicSharedMemorySize, P_SMEM_BYTES);
    cudaFuncSetAttribute(wgemm_tc_kernel, cudaFuncAttributeMaxDynamicSharedMemorySize, WG_SMEM_BYTES);
    cudaFuncSetAttribute(attn_mma_kernel, cudaFuncAttributeMaxDynamicSharedMemorySize, ATTN_SMEM_BYTES);

    prep_xt_kernel<<<dim3(NN / 32, CIN / 32, BB), 256>>>(x);
    proj_tc_kernel<<<dim3(NN / 128, CP / 128, BB), 256, P_SMEM_BYTES>>>(
        g_w, g_b, th_w, th_b, ph_w, ph_b);
    prep_qkg_kernel<<<dim3(NN / 32, CI / 32, BB * 3), 256>>>(
        g_gamma, g_beta, th_gamma, th_beta, ph_gamma, ph_beta);
    attn_mma_kernel<<<dim3(NN / 64, BB), 128, ATTN_SMEM_BYTES>>>();
    wgemm_tc_kernel<<<dim3(NN / 128, COUT / 128, BB), 256, WG_SMEM_BYTES>>>(x, W_w, W_b);
    finalize_kernel<<<(COUT * BB * NN) / 256, 256>>>(bn_gamma, bn_beta, out);
}